// round 2
// baseline (speedup 1.0000x reference)
#include <cuda_runtime.h>
#include <math.h>

#define BB 4
#define CC 8
#define HH 192
#define WW 256
#define HWSZ (HH*WW)
#define GEOMW 0.01f

// Static device scratch (no allocations allowed)
__device__ float  g_N0 [BB*3 *HWSZ];
__device__ float  g_dIx[BB*CC*HWSZ];
__device__ float  g_dIy[BB*CC*HWSZ];
__device__ double g_pose[BB*16];
__device__ double g_acc [BB*27];

__global__ void init_kernel(const float* __restrict__ pose_in) {
    int i = threadIdx.x;
    if (i < BB*16) g_pose[i] = (double)pose_in[i];
    if (i < BB*27) g_acc[i]  = 0.0;
}

__global__ void precompute_kernel(const float* __restrict__ I0,
                                  const float* __restrict__ depth0,
                                  const float* __restrict__ intr) {
    int pix = blockIdx.x*blockDim.x + threadIdx.x;
    int b = blockIdx.y;
    if (pix >= HWSZ) return;
    int x = pix & (WW-1);
    int y = pix / WW;
    float fx = intr[b*4+0], fy = intr[b*4+1], cx = intr[b*4+2], cy = intr[b*4+3];
    const float* d0 = depth0 + b*HWSZ;
    int xm = (x>0)? x-1 : 0, xp = (x<WW-1)? x+1 : WW-1;
    int ym = (y>0)? y-1 : 0, yp = (y<HH-1)? y+1 : HH-1;

    float dxm = d0[y*WW+xm], dxp = d0[y*WW+xp];
    float dym = d0[ym*WW+x], dyp = d0[yp*WW+x];

    // vertices at 4 clamped neighbors (edge-padded central diff)
    float vxm0=((float)xm-cx)/fx*dxm, vxm1=((float)y -cy)/fy*dxm, vxm2=dxm;
    float vxp0=((float)xp-cx)/fx*dxp, vxp1=((float)y -cy)/fy*dxp, vxp2=dxp;
    float vym0=((float)x -cx)/fx*dym, vym1=((float)ym-cy)/fy*dym, vym2=dym;
    float vyp0=((float)x -cx)/fx*dyp, vyp1=((float)yp-cy)/fy*dyp, vyp2=dyp;

    float ax=(vxp0-vxm0)*0.5f, ay=(vxp1-vxm1)*0.5f, az=(vxp2-vxm2)*0.5f;
    float bx=(vyp0-vym0)*0.5f, by=(vyp1-vym1)*0.5f, bz=(vyp2-vym2)*0.5f;

    float nx = ay*bz - az*by;
    float ny = az*bx - ax*bz;
    float nz = ax*by - ay*bx;
    float inv = 1.0f/sqrtf(nx*nx+ny*ny+nz*nz + 1e-12f);
    g_N0[(b*3+0)*HWSZ+pix] = nx*inv;
    g_N0[(b*3+1)*HWSZ+pix] = ny*inv;
    g_N0[(b*3+2)*HWSZ+pix] = nz*inv;

    #pragma unroll
    for (int c=0;c<CC;c++){
        const float* Ic = I0 + (size_t)(b*CC+c)*HWSZ;
        g_dIx[(b*CC+c)*HWSZ+pix] = (Ic[y*WW+xp]-Ic[y*WW+xm])*0.5f;
        g_dIy[(b*CC+c)*HWSZ+pix] = (Ic[yp*WW+x]-Ic[ym*WW+x])*0.5f;
    }
}

__device__ __forceinline__ void accum_res(float* acc, const float J[6], float r) {
    float ar = fabsf(r);
    float w  = (ar <= 0.5f) ? 1.0f : 0.5f/fmaxf(ar, 1e-12f);
    float wr = w*r;
    #pragma unroll
    for (int i=0;i<6;i++) acc[i] += J[i]*wr;
    int k=6;
    #pragma unroll
    for (int i=0;i<6;i++){
        float wJi = w*J[i];
        #pragma unroll
        for (int j=i;j<6;j++){
            acc[k] += wJi*J[j];
            k++;
        }
    }
}

__global__ void __launch_bounds__(256) accum_kernel(
    const float* __restrict__ I0, const float* __restrict__ I1,
    const float* __restrict__ depth0, const float* __restrict__ depth1,
    const float* __restrict__ intr)
{
    int pix = blockIdx.x*256 + threadIdx.x;
    int b = blockIdx.y;

    float acc[27];
    #pragma unroll
    for (int k=0;k<27;k++) acc[k]=0.0f;

    const double* P = g_pose + b*16;
    float R00=(float)P[0],  R01=(float)P[1],  R02=(float)P[2],  t0=(float)P[3];
    float R10=(float)P[4],  R11=(float)P[5],  R12=(float)P[6],  t1=(float)P[7];
    float R20=(float)P[8],  R21=(float)P[9],  R22=(float)P[10], t2=(float)P[11];

    int x = pix & (WW-1), y = pix / WW;
    float fx = intr[b*4+0], fy = intr[b*4+1], cx = intr[b*4+2], cy = intr[b*4+3];

    float d1  = depth1[b*HWSZ+pix];
    float d0c = depth0[b*HWSZ+pix];

    float Vx = ((float)x-cx)/fx*d1;
    float Vy = ((float)y-cy)/fy*d1;
    float Vz = d1;

    float Xx = R00*Vx+R01*Vy+R02*Vz+t0;
    float Xy = R10*Vx+R11*Vy+R12*Vz+t1;
    float Xz = R20*Vx+R21*Vy+R22*Vz+t2;

    bool  valid0 = Xz > 1e-8f;
    float zs = (fabsf(Xz) > 1e-8f) ? Xz : 1e-8f;
    float iz = 1.0f/zs;
    float u = fx*Xx*iz + cx;
    float v = fy*Xy*iz + cy;

    bool valid = (u>0.0f) && (u<(float)(WW-1)) && (v>0.0f) && (v<(float)(HH-1))
               && valid0 && (d0c>0.0f) && (d1>0.0f);

    if (valid) {
        float uf=floorf(u), vf=floorf(v);
        int iu=(int)uf, iv=(int)vf;
        float du=u-uf, dv=v-vf;
        float w00=(1.0f-du)*(1.0f-dv), w10=du*(1.0f-dv), w01=(1.0f-du)*dv, w11=du*dv;
        int i00 = iv*WW+iu;

        float a  = Xx*iz, bq = Xy*iz;
        float fxz = fx*iz, fyz = fy*iz;
        float Jw0[6] = { -fx*a*bq,        fx*(1.0f+a*a),  -fx*bq, fxz, 0.0f, -fxz*a };
        float Jw1[6] = { -fy*(1.0f+bq*bq), fy*a*bq,        fy*a,  0.0f, fyz, -fyz*bq };

        // ---- photometric channels ----
        #pragma unroll
        for (int c=0;c<CC;c++){
            int pb = (b*CC+c)*HWSZ;
            const float* p  = I0   + pb;
            const float* gxp= g_dIx+ pb;
            const float* gyp= g_dIy+ pb;
            float i1v = I1[pb+pix];
            float s  = w00*p[i00]  +w10*p[i00+1]  +w01*p[i00+WW]  +w11*p[i00+WW+1];
            float gx = w00*gxp[i00]+w10*gxp[i00+1]+w01*gxp[i00+WW]+w11*gxp[i00+WW+1];
            float gy = w00*gyp[i00]+w10*gyp[i00+1]+w01*gyp[i00+WW]+w11*gyp[i00+WW+1];
            float r = i1v - s;
            float J[6];
            #pragma unroll
            for (int k=0;k<6;k++) J[k] = gx*Jw0[k] + gy*Jw1[k];
            accum_res(acc, J, r);
        }

        // ---- ICP channel ----
        const float* d0p = depth0 + b*HWSZ;
        float dc00=d0p[i00], dc10=d0p[i00+1], dc01=d0p[i00+WW], dc11=d0p[i00+WW+1];
        float pxl = ((float)iu    -cx)/fx, pxr = ((float)(iu+1)-cx)/fx;
        float pyt = ((float)iv    -cy)/fy, pyb = ((float)(iv+1)-cy)/fy;
        float rVx = w00*pxl*dc00 + w10*pxr*dc10 + w01*pxl*dc01 + w11*pxr*dc11;
        float rVy = w00*pyt*dc00 + w10*pyt*dc10 + w01*pyb*dc01 + w11*pyb*dc11;
        float rVz = w00*dc00 + w10*dc10 + w01*dc01 + w11*dc11;

        const float* n0 = g_N0 + b*3*HWSZ;
        float rNx = w00*n0[i00]        +w10*n0[i00+1]        +w01*n0[i00+WW]        +w11*n0[i00+WW+1];
        float rNy = w00*n0[i00+HWSZ]   +w10*n0[i00+1+HWSZ]   +w01*n0[i00+WW+HWSZ]   +w11*n0[i00+WW+1+HWSZ];
        float rNz = w00*n0[i00+2*HWSZ] +w10*n0[i00+1+2*HWSZ] +w01*n0[i00+WW+2*HWSZ] +w11*n0[i00+WW+1+2*HWSZ];

        float dfx = Xx - rVx, dfy = Xy - rVy, dfz = Xz - rVz;
        float dn = sqrtf(dfx*dfx+dfy*dfy+dfz*dfz + 1e-12f);
        bool occ = dn > 0.1f;     // inviews == inb == true here

        // n^T R
        float nR0 = rNx*R00 + rNy*R10 + rNz*R20;
        float nR1 = rNx*R01 + rNy*R11 + rNz*R21;
        float nR2 = rNx*R02 + rNy*R12 + rNz*R22;

        float res = rNx*dfx + rNy*dfy + rNz*dfz;

        float sd0 = d1 * (5.5f/525.0f);
        float sd2 = d1*d1 * (0.4f/(525.0f*1.2f));
        float cov = (nR0*nR0 + nR1*nR1)*sd0*sd0 + nR2*nR2*sd2*sd2;
        float sigma = sqrtf(cov + 1e-8f);
        float isig = 1.0f/(sigma + 1e-8f);

        res *= isig;
        if (occ) res = 1e-6f;

        // Jrot = (n^T R) x V1 ; JFp = [Jrot, -nR]; J_Z = -JFp*isig; J = GEOM_W*J_Z
        float Jr0 = nR1*Vz - nR2*Vy;
        float Jr1 = nR2*Vx - nR0*Vz;
        float Jr2 = nR0*Vy - nR1*Vx;
        float gis = GEOMW*isig;
        float J[6] = { -Jr0*gis, -Jr1*gis, -Jr2*gis, nR0*gis, nR1*gis, nR2*gis };
        float r = -GEOMW * res;
        accum_res(acc, J, r);
    }

    // ---- block reduction: warp shuffle -> shared double -> global atomics ----
    __shared__ double sred[27];
    if (threadIdx.x < 27) sred[threadIdx.x] = 0.0;
    __syncthreads();
    #pragma unroll
    for (int k=0;k<27;k++){
        double val = (double)acc[k];
        #pragma unroll
        for (int off=16;off>0;off>>=1)
            val += __shfl_down_sync(0xffffffffu, val, off);
        if ((threadIdx.x & 31) == 0) atomicAdd(&sred[k], val);
    }
    __syncthreads();
    if (threadIdx.x < 27) atomicAdd(&g_acc[b*27+threadIdx.x], sred[threadIdx.x]);
}

__global__ void solve_kernel(float* __restrict__ out, int write_out) {
    int b = threadIdx.x;
    if (b >= BB) return;
    double* a = g_acc + b*27;

    double M[6][7];
    {
        double Hm[6][6];
        int k=6;
        for (int i=0;i<6;i++)
            for (int j=i;j<6;j++){ Hm[i][j]=a[k]; Hm[j][i]=a[k]; k++; }
        for (int i=0;i<6;i++) Hm[i][i] += 1e-6;
        for (int i=0;i<6;i++){
            for (int j=0;j<6;j++) M[i][j]=Hm[i][j];
            M[i][6]=a[i];
        }
    }
    // Gaussian elimination with partial pivoting
    for (int col=0; col<6; col++){
        int piv=col; double best=fabs(M[col][col]);
        for (int r2=col+1;r2<6;r2++){ double vv=fabs(M[r2][col]); if (vv>best){best=vv;piv=r2;} }
        if (piv!=col)
            for (int j=0;j<7;j++){ double tmp=M[col][j]; M[col][j]=M[piv][j]; M[piv][j]=tmp; }
        double ip = 1.0/M[col][col];
        for (int r2=col+1;r2<6;r2++){
            double f = M[r2][col]*ip;
            for (int j=col;j<7;j++) M[r2][j] -= f*M[col][j];
        }
    }
    double xi[6];
    for (int i=5;i>=0;i--){
        double s = M[i][6];
        for (int j=i+1;j<6;j++) s -= M[i][j]*xi[j];
        xi[i] = s/M[i][i];
    }

    // se(3) exp
    double w0=xi[0],w1=xi[1],w2=xi[2],v0=xi[3],v1=xi[4],v2=xi[5];
    double th2 = w0*w0+w1*w1+w2*w2;
    double A,Bc,Cc;
    if (th2 < 1e-8){
        A = 1.0 - th2/6.0; Bc = 0.5 - th2/24.0; Cc = 1.0/6.0 - th2/120.0;
    } else {
        double th = sqrt(th2);
        double s = sin(th), cth = cos(th);
        A = s/th; Bc = (1.0-cth)/th2; Cc = (th-s)/(th2*th);
    }
    double K[3][3] = {{0,-w2,w1},{w2,0,-w0},{-w1,w0,0}};
    double K2[3][3];
    for (int i=0;i<3;i++)
        for (int j=0;j<3;j++)
            K2[i][j] = K[i][0]*K[0][j]+K[i][1]*K[1][j]+K[i][2]*K[2][j];
    double T[4][4];
    double Vm[3][3];
    for (int i=0;i<3;i++)
        for (int j=0;j<3;j++){
            double I = (i==j)?1.0:0.0;
            T[i][j]  = I + A*K[i][j] + Bc*K2[i][j];
            Vm[i][j] = I + Bc*K[i][j] + Cc*K2[i][j];
        }
    T[0][3] = Vm[0][0]*v0+Vm[0][1]*v1+Vm[0][2]*v2;
    T[1][3] = Vm[1][0]*v0+Vm[1][1]*v1+Vm[1][2]*v2;
    T[2][3] = Vm[2][0]*v0+Vm[2][1]*v1+Vm[2][2]*v2;
    T[3][0]=0.0; T[3][1]=0.0; T[3][2]=0.0; T[3][3]=1.0;

    double* Pg = g_pose + b*16;
    double Pold[4][4];
    for (int i=0;i<4;i++)
        for (int j=0;j<4;j++) Pold[i][j] = Pg[i*4+j];
    double Pn[4][4];
    for (int i=0;i<4;i++)
        for (int j=0;j<4;j++){
            double s=0.0;
            for (int k=0;k<4;k++) s += T[i][k]*Pold[k][j];
            Pn[i][j]=s;
        }
    for (int i=0;i<4;i++)
        for (int j=0;j<4;j++) Pg[i*4+j] = Pn[i][j];

    for (int k=0;k<27;k++) a[k]=0.0;

    if (write_out){
        for (int i=0;i<4;i++)
            for (int j=0;j<4;j++)
                out[b*16 + i*4 + j] = (float)Pn[i][j];
    }
}

extern "C" void kernel_launch(void* const* d_in, const int* in_sizes, int n_in,
                              void* d_out, int out_size) {
    const float* pose   = (const float*)d_in[0];
    const float* I0     = (const float*)d_in[1];
    const float* I1     = (const float*)d_in[2];
    const float* intr   = (const float*)d_in[5];
    const float* depth0 = (const float*)d_in[6];
    const float* depth1 = (const float*)d_in[7];
    (void)in_sizes; (void)n_in; (void)out_size;

    init_kernel<<<1,128>>>(pose);
    dim3 grid(HWSZ/256, BB);
    precompute_kernel<<<grid,256>>>(I0, depth0, intr);
    for (int it=0; it<3; it++){
        accum_kernel<<<grid,256>>>(I0, I1, depth0, depth1, intr);
        solve_kernel<<<1,32>>>((float*)d_out, (it==2) ? 1 : 0);
    }
}

// round 3
// speedup vs baseline: 1.0630x; 1.0630x over previous
#include <cuda_runtime.h>
#include <math.h>

#define BB 4
#define CC 8
#define HH 192
#define WW 256
#define HWSZ (HH*WW)
#define GEOMW 0.01f
#define NBLKX (HWSZ/256)   // 192 blocks per batch

// Static device scratch (no allocations allowed)
__device__ float4 g_pack[BB*CC*HWSZ];   // {I0, dIx, dIy, 0}, layout [b][c][pix]
__device__ float4 g_icp [BB*HWSZ];      // {nx, ny, nz, depth0}, layout [b][pix]
__device__ float  g_pose[BB*16];
__device__ double g_acc [BB*27];
__device__ int    g_cnt [BB];

__global__ void __launch_bounds__(256) precompute_kernel(
    const float* __restrict__ I0, const float* __restrict__ depth0,
    const float* __restrict__ intr, const float* __restrict__ pose_in)
{
    int pix = blockIdx.x*256 + threadIdx.x;
    int b = blockIdx.y;

    // fold init into block (0,0): nothing in this launch reads these
    if (blockIdx.x == 0 && b == 0) {
        int i = threadIdx.x;
        if (i < BB*16) g_pose[i] = pose_in[i];
        if (i < BB*27) g_acc[i]  = 0.0;
        if (i < BB)    g_cnt[i]  = 0;
    }

    int x = pix & (WW-1);
    int y = pix / WW;
    float fx = intr[b*4+0], fy = intr[b*4+1], cx = intr[b*4+2], cy = intr[b*4+3];
    const float* d0 = depth0 + b*HWSZ;
    int xm = (x>0)? x-1 : 0, xp = (x<WW-1)? x+1 : WW-1;
    int ym = (y>0)? y-1 : 0, yp = (y<HH-1)? y+1 : HH-1;

    float dxm = d0[y*WW+xm], dxp = d0[y*WW+xp];
    float dym = d0[ym*WW+x], dyp = d0[yp*WW+x];
    float dc  = d0[pix];

    // vertices at 4 clamped neighbors (edge-padded central diff)
    float vxm0=((float)xm-cx)/fx*dxm, vxm1=((float)y -cy)/fy*dxm, vxm2=dxm;
    float vxp0=((float)xp-cx)/fx*dxp, vxp1=((float)y -cy)/fy*dxp, vxp2=dxp;
    float vym0=((float)x -cx)/fx*dym, vym1=((float)ym-cy)/fy*dym, vym2=dym;
    float vyp0=((float)x -cx)/fx*dyp, vyp1=((float)yp-cy)/fy*dyp, vyp2=dyp;

    float ax=(vxp0-vxm0)*0.5f, ay=(vxp1-vxm1)*0.5f, az=(vxp2-vxm2)*0.5f;
    float bx=(vyp0-vym0)*0.5f, by=(vyp1-vym1)*0.5f, bz=(vyp2-vym2)*0.5f;

    float nx = ay*bz - az*by;
    float ny = az*bx - ax*bz;
    float nz = ax*by - ay*bx;
    float inv = 1.0f/sqrtf(nx*nx+ny*ny+nz*nz + 1e-12f);
    g_icp[b*HWSZ + pix] = make_float4(nx*inv, ny*inv, nz*inv, dc);

    #pragma unroll
    for (int c=0;c<CC;c++){
        const float* Ic = I0 + (size_t)(b*CC+c)*HWSZ;
        float gx = (Ic[y*WW+xp]-Ic[y*WW+xm])*0.5f;
        float gy = (Ic[yp*WW+x]-Ic[ym*WW+x])*0.5f;
        g_pack[(b*CC+c)*HWSZ + pix] = make_float4(Ic[pix], gx, gy, 0.0f);
    }
}

__device__ __forceinline__ void accum_res(float* acc, const float J[6], float r) {
    float ar = fabsf(r);
    float w  = (ar <= 0.5f) ? 1.0f : 0.5f/fmaxf(ar, 1e-12f);
    float wr = w*r;
    #pragma unroll
    for (int i=0;i<6;i++) acc[i] += J[i]*wr;
    int k=6;
    #pragma unroll
    for (int i=0;i<6;i++){
        float wJi = w*J[i];
        #pragma unroll
        for (int j=i;j<6;j++){
            acc[k] += wJi*J[j];
            k++;
        }
    }
}

// float 6x6 solve + se3 exp + pose update, run by one thread
__device__ void solve_batch(int b, float* __restrict__ out, int write_out) {
    double* a = g_acc + b*27;
    float M[6][7];
    {
        int k=6;
        for (int i=0;i<6;i++)
            for (int j=i;j<6;j++){ float v=(float)a[k]; M[i][j]=v; M[j][i]=v; k++; }
        for (int i=0;i<6;i++){ M[i][i] += 1e-6f; M[i][6] = (float)a[i]; }
    }
    // Gaussian elimination with partial pivoting
    for (int col=0; col<6; col++){
        int piv=col; float best=fabsf(M[col][col]);
        for (int r2=col+1;r2<6;r2++){ float vv=fabsf(M[r2][col]); if (vv>best){best=vv;piv=r2;} }
        if (piv!=col)
            for (int j=0;j<7;j++){ float tmp=M[col][j]; M[col][j]=M[piv][j]; M[piv][j]=tmp; }
        float ip = 1.0f/M[col][col];
        for (int r2=col+1;r2<6;r2++){
            float f = M[r2][col]*ip;
            for (int j=col;j<7;j++) M[r2][j] -= f*M[col][j];
        }
    }
    float xi[6];
    for (int i=5;i>=0;i--){
        float s = M[i][6];
        for (int j=i+1;j<6;j++) s -= M[i][j]*xi[j];
        xi[i] = s/M[i][i];
    }

    // se(3) exp (float, matching float32 reference)
    float w0=xi[0],w1=xi[1],w2=xi[2],v0=xi[3],v1=xi[4],v2=xi[5];
    float th2 = w0*w0+w1*w1+w2*w2;
    float A,Bc,Cc;
    if (th2 < 1e-8f){
        A = 1.0f - th2/6.0f; Bc = 0.5f - th2/24.0f; Cc = 1.0f/6.0f - th2/120.0f;
    } else {
        float th = sqrtf(th2);
        float s, cth;
        sincosf(th, &s, &cth);
        A = s/th; Bc = (1.0f-cth)/th2; Cc = (th-s)/(th2*th);
    }
    float K[3][3] = {{0.f,-w2,w1},{w2,0.f,-w0},{-w1,w0,0.f}};
    float K2[3][3];
    for (int i=0;i<3;i++)
        for (int j=0;j<3;j++)
            K2[i][j] = K[i][0]*K[0][j]+K[i][1]*K[1][j]+K[i][2]*K[2][j];
    float T[4][4];
    float Vm[3][3];
    for (int i=0;i<3;i++)
        for (int j=0;j<3;j++){
            float I = (i==j)?1.0f:0.0f;
            T[i][j]  = I + A*K[i][j] + Bc*K2[i][j];
            Vm[i][j] = I + Bc*K[i][j] + Cc*K2[i][j];
        }
    T[0][3] = Vm[0][0]*v0+Vm[0][1]*v1+Vm[0][2]*v2;
    T[1][3] = Vm[1][0]*v0+Vm[1][1]*v1+Vm[1][2]*v2;
    T[2][3] = Vm[2][0]*v0+Vm[2][1]*v1+Vm[2][2]*v2;
    T[3][0]=0.0f; T[3][1]=0.0f; T[3][2]=0.0f; T[3][3]=1.0f;

    float* Pg = g_pose + b*16;
    float Pold[4][4];
    for (int i=0;i<4;i++)
        for (int j=0;j<4;j++) Pold[i][j] = Pg[i*4+j];
    float Pn[4][4];
    for (int i=0;i<4;i++)
        for (int j=0;j<4;j++){
            float s=0.0f;
            for (int k=0;k<4;k++) s += T[i][k]*Pold[k][j];
            Pn[i][j]=s;
        }
    for (int i=0;i<4;i++)
        for (int j=0;j<4;j++) Pg[i*4+j] = Pn[i][j];

    for (int k=0;k<27;k++) a[k]=0.0;

    if (write_out){
        for (int i=0;i<4;i++)
            for (int j=0;j<4;j++)
                out[b*16 + i*4 + j] = Pn[i][j];
    }
}

__global__ void __launch_bounds__(256) accumsolve_kernel(
    const float* __restrict__ I1, const float* __restrict__ depth1,
    const float* __restrict__ intr, float* __restrict__ out, int write_out)
{
    int pix = blockIdx.x*256 + threadIdx.x;
    int b = blockIdx.y;

    float acc[27];
    #pragma unroll
    for (int k=0;k<27;k++) acc[k]=0.0f;

    const float* P = g_pose + b*16;
    float R00=P[0],  R01=P[1],  R02=P[2],  t0=P[3];
    float R10=P[4],  R11=P[5],  R12=P[6],  t1=P[7];
    float R20=P[8],  R21=P[9],  R22=P[10], t2=P[11];

    int x = pix & (WW-1), y = pix / WW;
    float fx = intr[b*4+0], fy = intr[b*4+1], cx = intr[b*4+2], cy = intr[b*4+3];

    float d1 = depth1[b*HWSZ+pix];
    float4 icpc = g_icp[b*HWSZ+pix];
    float d0c = icpc.w;

    float Vx = ((float)x-cx)/fx*d1;
    float Vy = ((float)y-cy)/fy*d1;
    float Vz = d1;

    float Xx = R00*Vx+R01*Vy+R02*Vz+t0;
    float Xy = R10*Vx+R11*Vy+R12*Vz+t1;
    float Xz = R20*Vx+R21*Vy+R22*Vz+t2;

    bool  valid0 = Xz > 1e-8f;
    float zs = (fabsf(Xz) > 1e-8f) ? Xz : 1e-8f;
    float iz = 1.0f/zs;
    float u = fx*Xx*iz + cx;
    float v = fy*Xy*iz + cy;

    bool valid = (u>0.0f) && (u<(float)(WW-1)) && (v>0.0f) && (v<(float)(HH-1))
               && valid0 && (d0c>0.0f) && (d1>0.0f);

    if (valid) {
        float uf=floorf(u), vf=floorf(v);
        int iu=(int)uf, iv=(int)vf;
        float du=u-uf, dv=v-vf;
        float w00=(1.0f-du)*(1.0f-dv), w10=du*(1.0f-dv), w01=(1.0f-du)*dv, w11=du*dv;
        int i00 = iv*WW+iu;

        float a  = Xx*iz, bq = Xy*iz;
        float fxz = fx*iz, fyz = fy*iz;
        float Jw0[6] = { -fx*a*bq,        fx*(1.0f+a*a),  -fx*bq, fxz, 0.0f, -fxz*a };
        float Jw1[6] = { -fy*(1.0f+bq*bq), fy*a*bq,        fy*a,  0.0f, fyz, -fyz*bq };

        // ---- photometric channels: one float4 gather per corner per channel ----
        #pragma unroll
        for (int c=0;c<CC;c++){
            const float4* pk = g_pack + (size_t)(b*CC+c)*HWSZ;
            float4 q00 = pk[i00];
            float4 q10 = pk[i00+1];
            float4 q01 = pk[i00+WW];
            float4 q11 = pk[i00+WW+1];
            float i1v = I1[(size_t)(b*CC+c)*HWSZ + pix];
            float s  = w00*q00.x + w10*q10.x + w01*q01.x + w11*q11.x;
            float gx = w00*q00.y + w10*q10.y + w01*q01.y + w11*q11.y;
            float gy = w00*q00.z + w10*q10.z + w01*q01.z + w11*q11.z;
            float r = i1v - s;
            float J[6];
            #pragma unroll
            for (int k=0;k<6;k++) J[k] = gx*Jw0[k] + gy*Jw1[k];
            accum_res(acc, J, r);
        }

        // ---- ICP channel: one float4 gather per corner ----
        const float4* ip = g_icp + b*HWSZ;
        float4 e00 = ip[i00];
        float4 e10 = ip[i00+1];
        float4 e01 = ip[i00+WW];
        float4 e11 = ip[i00+WW+1];

        float pxl = ((float)iu    -cx)/fx, pxr = ((float)(iu+1)-cx)/fx;
        float pyt = ((float)iv    -cy)/fy, pyb = ((float)(iv+1)-cy)/fy;
        float rVx = w00*pxl*e00.w + w10*pxr*e10.w + w01*pxl*e01.w + w11*pxr*e11.w;
        float rVy = w00*pyt*e00.w + w10*pyt*e10.w + w01*pyb*e01.w + w11*pyb*e11.w;
        float rVz = w00*e00.w + w10*e10.w + w01*e01.w + w11*e11.w;

        float rNx = w00*e00.x + w10*e10.x + w01*e01.x + w11*e11.x;
        float rNy = w00*e00.y + w10*e10.y + w01*e01.y + w11*e11.y;
        float rNz = w00*e00.z + w10*e10.z + w01*e01.z + w11*e11.z;

        float dfx = Xx - rVx, dfy = Xy - rVy, dfz = Xz - rVz;
        float dn = sqrtf(dfx*dfx+dfy*dfy+dfz*dfz + 1e-12f);
        bool occ = dn > 0.1f;     // inviews == inb == true here

        // n^T R
        float nR0 = rNx*R00 + rNy*R10 + rNz*R20;
        float nR1 = rNx*R01 + rNy*R11 + rNz*R21;
        float nR2 = rNx*R02 + rNy*R12 + rNz*R22;

        float res = rNx*dfx + rNy*dfy + rNz*dfz;

        float sd0 = d1 * (5.5f/525.0f);
        float sd2 = d1*d1 * (0.4f/(525.0f*1.2f));
        float cov = (nR0*nR0 + nR1*nR1)*sd0*sd0 + nR2*nR2*sd2*sd2;
        float sigma = sqrtf(cov + 1e-8f);
        float isig = 1.0f/(sigma + 1e-8f);

        res *= isig;
        if (occ) res = 1e-6f;

        float Jr0 = nR1*Vz - nR2*Vy;
        float Jr1 = nR2*Vx - nR0*Vz;
        float Jr2 = nR0*Vy - nR1*Vx;
        float gis = GEOMW*isig;
        float J[6] = { -Jr0*gis, -Jr1*gis, -Jr2*gis, nR0*gis, nR1*gis, nR2*gis };
        float r = -GEOMW * res;
        accum_res(acc, J, r);
    }

    // ---- block reduction: warp shuffle -> shared double -> global atomics ----
    __shared__ double sred[27];
    __shared__ bool amLast;
    if (threadIdx.x < 27) sred[threadIdx.x] = 0.0;
    __syncthreads();
    #pragma unroll
    for (int k=0;k<27;k++){
        double val = (double)acc[k];
        #pragma unroll
        for (int off=16;off>0;off>>=1)
            val += __shfl_down_sync(0xffffffffu, val, off);
        if ((threadIdx.x & 31) == 0) atomicAdd(&sred[k], val);
    }
    __syncthreads();
    if (threadIdx.x < 27) atomicAdd(&g_acc[b*27+threadIdx.x], sred[threadIdx.x]);

    // ---- last block for this batch performs the solve ----
    __threadfence();
    __syncthreads();
    if (threadIdx.x == 0){
        int prev = atomicAdd(&g_cnt[b], 1);
        amLast = (prev == NBLKX-1);
    }
    __syncthreads();
    if (amLast && threadIdx.x == 0){
        __threadfence();               // acquire: see all batches' g_acc atomics
        solve_batch(b, out, write_out);
        g_cnt[b] = 0;                  // reset for next iteration / next replay
    }
}

extern "C" void kernel_launch(void* const* d_in, const int* in_sizes, int n_in,
                              void* d_out, int out_size) {
    const float* pose   = (const float*)d_in[0];
    const float* I0     = (const float*)d_in[1];
    const float* I1     = (const float*)d_in[2];
    const float* intr   = (const float*)d_in[5];
    const float* depth0 = (const float*)d_in[6];
    const float* depth1 = (const float*)d_in[7];
    (void)in_sizes; (void)n_in; (void)out_size;

    dim3 grid(NBLKX, BB);
    precompute_kernel<<<grid,256>>>(I0, depth0, intr, pose);
    for (int it=0; it<3; it++){
        accumsolve_kernel<<<grid,256>>>(I1, depth1, intr, (float*)d_out, (it==2) ? 1 : 0);
    }
}

// round 7
// speedup vs baseline: 1.1542x; 1.0858x over previous
#include <cuda_runtime.h>
#include <math.h>

#define BB 4
#define CC 8
#define HH 192
#define WW 256
#define HWSZ (HH*WW)
#define GEOMW 0.01f
#define NBLKX (HWSZ/256)   // 192 blocks per batch

// Static device scratch (no allocations allowed)
__device__ float4 g_pack[BB*CC*HWSZ];   // {I0, dIx, dIy, 0}, layout [b][c][pix]
__device__ float4 g_icp [BB*HWSZ];      // {nx, ny, nz, depth0}, layout [b][pix]
__device__ float  g_pose[BB*16];
__device__ double g_acc [BB*27];
__device__ int    g_cnt [BB];

__global__ void __launch_bounds__(256) precompute_kernel(
    const float* __restrict__ I0, const float* __restrict__ depth0,
    const float* __restrict__ intr, const float* __restrict__ pose_in)
{
    int pix = blockIdx.x*256 + threadIdx.x;
    int b = blockIdx.y;

    if (blockIdx.x == 0 && b == 0) {
        int i = threadIdx.x;
        if (i < BB*16) g_pose[i] = pose_in[i];
        if (i < BB*27) g_acc[i]  = 0.0;
        if (i < BB)    g_cnt[i]  = 0;
    }

    int x = pix & (WW-1);
    int y = pix / WW;
    float fx = intr[b*4+0], fy = intr[b*4+1], cx = intr[b*4+2], cy = intr[b*4+3];
    const float* d0 = depth0 + b*HWSZ;
    int xm = (x>0)? x-1 : 0, xp = (x<WW-1)? x+1 : WW-1;
    int ym = (y>0)? y-1 : 0, yp = (y<HH-1)? y+1 : HH-1;

    float dxm = d0[y*WW+xm], dxp = d0[y*WW+xp];
    float dym = d0[ym*WW+x], dyp = d0[yp*WW+x];
    float dc  = d0[pix];

    float vxm0=((float)xm-cx)/fx*dxm, vxm1=((float)y -cy)/fy*dxm, vxm2=dxm;
    float vxp0=((float)xp-cx)/fx*dxp, vxp1=((float)y -cy)/fy*dxp, vxp2=dxp;
    float vym0=((float)x -cx)/fx*dym, vym1=((float)ym-cy)/fy*dym, vym2=dym;
    float vyp0=((float)x -cx)/fx*dyp, vyp1=((float)yp-cy)/fy*dyp, vyp2=dyp;

    float ax=(vxp0-vxm0)*0.5f, ay=(vxp1-vxm1)*0.5f, az=(vxp2-vxm2)*0.5f;
    float bx=(vyp0-vym0)*0.5f, by=(vyp1-vym1)*0.5f, bz=(vyp2-vym2)*0.5f;

    float nx = ay*bz - az*by;
    float ny = az*bx - ax*bz;
    float nz = ax*by - ay*bx;
    float inv = 1.0f/sqrtf(nx*nx+ny*ny+nz*nz + 1e-12f);
    g_icp[b*HWSZ + pix] = make_float4(nx*inv, ny*inv, nz*inv, dc);

    #pragma unroll
    for (int c=0;c<CC;c++){
        const float* Ic = I0 + (size_t)(b*CC+c)*HWSZ;
        float gx = (Ic[y*WW+xp]-Ic[y*WW+xm])*0.5f;
        float gy = (Ic[yp*WW+x]-Ic[ym*WW+x])*0.5f;
        g_pack[(b*CC+c)*HWSZ + pix] = make_float4(Ic[pix], gx, gy, 0.0f);
    }
}

// float 6x6 solve + se3 exp + pose update, run by one thread
__device__ void solve_batch(int b, float* __restrict__ out, int write_out) {
    double* a = g_acc + b*27;
    float M[6][7];
    {
        int k=6;
        for (int i=0;i<6;i++)
            for (int j=i;j<6;j++){ float v=(float)a[k]; M[i][j]=v; M[j][i]=v; k++; }
        for (int i=0;i<6;i++){ M[i][i] += 1e-6f; M[i][6] = (float)a[i]; }
    }
    for (int col=0; col<6; col++){
        int piv=col; float best=fabsf(M[col][col]);
        for (int r2=col+1;r2<6;r2++){ float vv=fabsf(M[r2][col]); if (vv>best){best=vv;piv=r2;} }
        if (piv!=col)
            for (int j=0;j<7;j++){ float tmp=M[col][j]; M[col][j]=M[piv][j]; M[piv][j]=tmp; }
        float ip = 1.0f/M[col][col];
        for (int r2=col+1;r2<6;r2++){
            float f = M[r2][col]*ip;
            for (int j=col;j<7;j++) M[r2][j] -= f*M[col][j];
        }
    }
    float xi[6];
    for (int i=5;i>=0;i--){
        float s = M[i][6];
        for (int j=i+1;j<6;j++) s -= M[i][j]*xi[j];
        xi[i] = s/M[i][i];
    }

    float w0=xi[0],w1=xi[1],w2=xi[2],v0=xi[3],v1=xi[4],v2=xi[5];
    float th2 = w0*w0+w1*w1+w2*w2;
    float A,Bc,Cc;
    if (th2 < 1e-8f){
        A = 1.0f - th2/6.0f; Bc = 0.5f - th2/24.0f; Cc = 1.0f/6.0f - th2/120.0f;
    } else {
        float th = sqrtf(th2);
        float s, cth;
        sincosf(th, &s, &cth);
        A = s/th; Bc = (1.0f-cth)/th2; Cc = (th-s)/(th2*th);
    }
    float K[3][3] = {{0.f,-w2,w1},{w2,0.f,-w0},{-w1,w0,0.f}};
    float K2[3][3];
    for (int i=0;i<3;i++)
        for (int j=0;j<3;j++)
            K2[i][j] = K[i][0]*K[0][j]+K[i][1]*K[1][j]+K[i][2]*K[2][j];
    float T[4][4];
    float Vm[3][3];
    for (int i=0;i<3;i++)
        for (int j=0;j<3;j++){
            float I = (i==j)?1.0f:0.0f;
            T[i][j]  = I + A*K[i][j] + Bc*K2[i][j];
            Vm[i][j] = I + Bc*K[i][j] + Cc*K2[i][j];
        }
    T[0][3] = Vm[0][0]*v0+Vm[0][1]*v1+Vm[0][2]*v2;
    T[1][3] = Vm[1][0]*v0+Vm[1][1]*v1+Vm[1][2]*v2;
    T[2][3] = Vm[2][0]*v0+Vm[2][1]*v1+Vm[2][2]*v2;
    T[3][0]=0.0f; T[3][1]=0.0f; T[3][2]=0.0f; T[3][3]=1.0f;

    float* Pg = g_pose + b*16;
    float Pold[4][4];
    for (int i=0;i<4;i++)
        for (int j=0;j<4;j++) Pold[i][j] = Pg[i*4+j];
    float Pn[4][4];
    for (int i=0;i<4;i++)
        for (int j=0;j<4;j++){
            float s=0.0f;
            for (int k=0;k<4;k++) s += T[i][k]*Pold[k][j];
            Pn[i][j]=s;
        }
    for (int i=0;i<4;i++)
        for (int j=0;j<4;j++) Pg[i*4+j] = Pn[i][j];

    for (int k=0;k<27;k++) a[k]=0.0;

    if (write_out){
        for (int i=0;i<4;i++)
            for (int j=0;j<4;j++)
                out[b*16 + i*4 + j] = Pn[i][j];
    }
}

__global__ void __launch_bounds__(256,3) accumsolve_kernel(
    const float* __restrict__ I1, const float* __restrict__ depth1,
    const float* __restrict__ intr, float* __restrict__ out, int write_out)
{
    int pix = blockIdx.x*256 + threadIdx.x;
    int b = blockIdx.y;

    float acc[27];
    #pragma unroll
    for (int k=0;k<27;k++) acc[k]=0.0f;

    const float* P = g_pose + b*16;
    float R00=P[0],  R01=P[1],  R02=P[2],  t0=P[3];
    float R10=P[4],  R11=P[5],  R12=P[6],  t1=P[7];
    float R20=P[8],  R21=P[9],  R22=P[10], t2=P[11];

    int x = pix & (WW-1), y = pix / WW;
    float fx = intr[b*4+0], fy = intr[b*4+1], cx = intr[b*4+2], cy = intr[b*4+3];

    float d1 = depth1[b*HWSZ+pix];
    float4 icpc = g_icp[b*HWSZ+pix];
    float d0c = icpc.w;

    float Vx = ((float)x-cx)/fx*d1;
    float Vy = ((float)y-cy)/fy*d1;
    float Vz = d1;

    float Xx = R00*Vx+R01*Vy+R02*Vz+t0;
    float Xy = R10*Vx+R11*Vy+R12*Vz+t1;
    float Xz = R20*Vx+R21*Vy+R22*Vz+t2;

    bool  valid0 = Xz > 1e-8f;
    float zs = (fabsf(Xz) > 1e-8f) ? Xz : 1e-8f;
    float iz = __fdividef(1.0f, zs);
    float u = fx*Xx*iz + cx;
    float v = fy*Xy*iz + cy;

    bool valid = (u>0.0f) && (u<(float)(WW-1)) && (v>0.0f) && (v<(float)(HH-1))
               && valid0 && (d0c>0.0f) && (d1>0.0f);

    if (valid) {
        float uf=floorf(u), vf=floorf(v);
        int iu=(int)uf, iv=(int)vf;
        float du=u-uf, dv=v-vf;
        float w00=(1.0f-du)*(1.0f-dv), w10=du*(1.0f-dv), w01=(1.0f-du)*dv, w11=du*dv;
        int i00 = iv*WW+iu;

        float a  = Xx*iz, bq = Xy*iz;
        float fxz = fx*iz, fyz = fy*iz;
        // A = row0 of Jw (A[4]=0), B = row1 of Jw (B[3]=0)
        float A0=-fx*a*bq,         A1=fx*(1.0f+a*a), A2=-fx*bq, A3=fxz, A5=-fxz*a;
        float B0=-fy*(1.0f+bq*bq), B1=fy*a*bq,       B2=fy*a,   B4=fyz, B5=-fyz*bq;

        // front-load the 8 coalesced I1 reads
        float i1v[CC];
        #pragma unroll
        for (int c=0;c<CC;c++) i1v[c] = I1[(size_t)(b*CC+c)*HWSZ + pix];

        // ---- photometric channels: rank-2 sufficient statistics ----
        float Sxx=0.f, Sxy=0.f, Syy=0.f, Srx=0.f, Sry=0.f;
        #pragma unroll
        for (int c=0;c<CC;c++){
            const float4* pk = g_pack + (size_t)(b*CC+c)*HWSZ;
            float4 q00 = pk[i00];
            float4 q10 = pk[i00+1];
            float4 q01 = pk[i00+WW];
            float4 q11 = pk[i00+WW+1];
            float s  = w00*q00.x + w10*q10.x + w01*q01.x + w11*q11.x;
            float gx = w00*q00.y + w10*q10.y + w01*q01.y + w11*q11.y;
            float gy = w00*q00.z + w10*q10.z + w01*q01.z + w11*q11.z;
            float r = i1v[c] - s;
            float ar = fabsf(r);
            float w  = (ar <= 0.5f) ? 1.0f : __fdividef(0.5f, fmaxf(ar, 1e-12f));
            Sxx += w*gx*gx;
            Sxy += w*gx*gy;
            Syy += w*gy*gy;
            Srx += w*r*gx;
            Sry += w*r*gy;
        }

        // expand once into the 27 accumulators
        {
            float Av[6] = {A0,A1,A2,A3,0.f,A5};
            float Bv[6] = {B0,B1,B2,0.f,B4,B5};
            #pragma unroll
            for (int i=0;i<6;i++) acc[i] += Srx*Av[i] + Sry*Bv[i];
            int k=6;
            #pragma unroll
            for (int i=0;i<6;i++){
                float xA = Sxx*Av[i] + Sxy*Bv[i];
                float xB = Sxy*Av[i] + Syy*Bv[i];
                #pragma unroll
                for (int j=i;j<6;j++){
                    acc[k] += xA*Av[j] + xB*Bv[j];
                    k++;
                }
            }
        }

        // ---- ICP channel ----
        const float4* ip = g_icp + b*HWSZ;
        float4 e00 = ip[i00];
        float4 e10 = ip[i00+1];
        float4 e01 = ip[i00+WW];
        float4 e11 = ip[i00+WW+1];

        float pxl = ((float)iu    -cx)/fx, pxr = ((float)(iu+1)-cx)/fx;
        float pyt = ((float)iv    -cy)/fy, pyb = ((float)(iv+1)-cy)/fy;
        float rVx = w00*pxl*e00.w + w10*pxr*e10.w + w01*pxl*e01.w + w11*pxr*e11.w;
        float rVy = w00*pyt*e00.w + w10*pyt*e10.w + w01*pyb*e01.w + w11*pyb*e11.w;
        float rVz = w00*e00.w + w10*e10.w + w01*e01.w + w11*e11.w;

        float rNx = w00*e00.x + w10*e10.x + w01*e01.x + w11*e11.x;
        float rNy = w00*e00.y + w10*e10.y + w01*e01.y + w11*e11.y;
        float rNz = w00*e00.z + w10*e10.z + w01*e01.z + w11*e11.z;

        float dfx = Xx - rVx, dfy = Xy - rVy, dfz = Xz - rVz;
        float dn2 = dfx*dfx+dfy*dfy+dfz*dfz + 1e-12f;
        bool occ = dn2 > 0.01f;    // dn>0.1  (inviews == inb == true here)

        float nR0 = rNx*R00 + rNy*R10 + rNz*R20;
        float nR1 = rNx*R01 + rNy*R11 + rNz*R21;
        float nR2 = rNx*R02 + rNy*R12 + rNz*R22;

        float res = rNx*dfx + rNy*dfy + rNz*dfz;

        float sd0 = d1 * (5.5f/525.0f);
        float sd2 = d1*d1 * (0.4f/(525.0f*1.2f));
        float cov = (nR0*nR0 + nR1*nR1)*sd0*sd0 + nR2*nR2*sd2*sd2;
        float sigma = sqrtf(cov + 1e-8f);
        float isig = __fdividef(1.0f, sigma + 1e-8f);

        res *= isig;
        if (occ) res = 1e-6f;

        float Jr0 = nR1*Vz - nR2*Vy;
        float Jr1 = nR2*Vx - nR0*Vz;
        float Jr2 = nR0*Vy - nR1*Vx;
        float gis = GEOMW*isig;
        float J[6] = { -Jr0*gis, -Jr1*gis, -Jr2*gis, nR0*gis, nR1*gis, nR2*gis };
        float r = -GEOMW * res;
        {
            float ar = fabsf(r);
            float w  = (ar <= 0.5f) ? 1.0f : __fdividef(0.5f, fmaxf(ar, 1e-12f));
            float wr = w*r;
            #pragma unroll
            for (int i=0;i<6;i++) acc[i] += J[i]*wr;
            int k=6;
            #pragma unroll
            for (int i=0;i<6;i++){
                float wJi = w*J[i];
                #pragma unroll
                for (int j=i;j<6;j++){
                    acc[k] += wJi*J[j];
                    k++;
                }
            }
        }
    }

    // ---- block reduction: warp shuffle -> shared double -> global atomics ----
    __shared__ double sred[27];
    __shared__ bool amLast;
    if (threadIdx.x < 27) sred[threadIdx.x] = 0.0;
    __syncthreads();
    #pragma unroll
    for (int k=0;k<27;k++){
        double val = (double)acc[k];
        #pragma unroll
        for (int off=16;off>0;off>>=1)
            val += __shfl_down_sync(0xffffffffu, val, off);
        if ((threadIdx.x & 31) == 0) atomicAdd(&sred[k], val);
    }
    __syncthreads();
    if (threadIdx.x < 27) atomicAdd(&g_acc[b*27+threadIdx.x], sred[threadIdx.x]);

    // ---- last block for this batch performs the solve ----
    __threadfence();
    __syncthreads();
    if (threadIdx.x == 0){
        int prev = atomicAdd(&g_cnt[b], 1);
        amLast = (prev == NBLKX-1);
    }
    __syncthreads();
    if (amLast && threadIdx.x == 0){
        __threadfence();
        solve_batch(b, out, write_out);
        g_cnt[b] = 0;
    }
}

extern "C" void kernel_launch(void* const* d_in, const int* in_sizes, int n_in,
                              void* d_out, int out_size) {
    const float* pose   = (const float*)d_in[0];
    const float* I0     = (const float*)d_in[1];
    const float* I1     = (const float*)d_in[2];
    const float* intr   = (const float*)d_in[5];
    const float* depth0 = (const float*)d_in[6];
    const float* depth1 = (const float*)d_in[7];
    (void)in_sizes; (void)n_in; (void)out_size;

    dim3 grid(NBLKX, BB);
    precompute_kernel<<<grid,256>>>(I0, depth0, intr, pose);
    for (int it=0; it<3; it++){
        accumsolve_kernel<<<grid,256>>>(I1, depth1, intr, (float*)d_out, (it==2) ? 1 : 0);
    }
}

// round 8
// speedup vs baseline: 1.4336x; 1.2420x over previous
#include <cuda_runtime.h>
#include <math.h>

#define BB 4
#define CC 8
#define HH 192
#define WW 256
#define HWSZ (HH*WW)
#define GEOMW 0.01f
#define PIXPB 128                 // pixels per block (x2 channel groups = 256 threads)
#define NBLKX (HWSZ/PIXPB)        // 384 blocks per batch

// Static device scratch (no allocations allowed)
__device__ float4 g_pack[BB*CC*HWSZ];   // {I0, dIx, dIy, 0}, layout [b][c][pix]
__device__ float4 g_icp [BB*HWSZ];      // {nx, ny, nz, depth0}, layout [b][pix]
__device__ float  g_pose[BB*16];
__device__ double g_acc [BB*27];
__device__ int    g_cnt [BB];

__global__ void __launch_bounds__(256) precompute_kernel(
    const float* __restrict__ I0, const float* __restrict__ depth0,
    const float* __restrict__ intr, const float* __restrict__ pose_in)
{
    int pix = blockIdx.x*256 + threadIdx.x;
    int b = blockIdx.y;

    if (blockIdx.x == 0 && b == 0) {
        int i = threadIdx.x;
        if (i < BB*16) g_pose[i] = pose_in[i];
        if (i < BB*27) g_acc[i]  = 0.0;
        if (i < BB)    g_cnt[i]  = 0;
    }

    int x = pix & (WW-1);
    int y = pix / WW;
    float fx = intr[b*4+0], fy = intr[b*4+1], cx = intr[b*4+2], cy = intr[b*4+3];
    const float* d0 = depth0 + b*HWSZ;
    int xm = (x>0)? x-1 : 0, xp = (x<WW-1)? x+1 : WW-1;
    int ym = (y>0)? y-1 : 0, yp = (y<HH-1)? y+1 : HH-1;

    float dxm = d0[y*WW+xm], dxp = d0[y*WW+xp];
    float dym = d0[ym*WW+x], dyp = d0[yp*WW+x];
    float dc  = d0[pix];

    float vxm0=((float)xm-cx)/fx*dxm, vxm1=((float)y -cy)/fy*dxm, vxm2=dxm;
    float vxp0=((float)xp-cx)/fx*dxp, vxp1=((float)y -cy)/fy*dxp, vxp2=dxp;
    float vym0=((float)x -cx)/fx*dym, vym1=((float)ym-cy)/fy*dym, vym2=dym;
    float vyp0=((float)x -cx)/fx*dyp, vyp1=((float)yp-cy)/fy*dyp, vyp2=dyp;

    float ax=(vxp0-vxm0)*0.5f, ay=(vxp1-vxm1)*0.5f, az=(vxp2-vxm2)*0.5f;
    float bx=(vyp0-vym0)*0.5f, by=(vyp1-vym1)*0.5f, bz=(vyp2-vym2)*0.5f;

    float nx = ay*bz - az*by;
    float ny = az*bx - ax*bz;
    float nz = ax*by - ay*bx;
    float inv = 1.0f/sqrtf(nx*nx+ny*ny+nz*nz + 1e-12f);
    g_icp[b*HWSZ + pix] = make_float4(nx*inv, ny*inv, nz*inv, dc);

    #pragma unroll
    for (int c=0;c<CC;c++){
        const float* Ic = I0 + (size_t)(b*CC+c)*HWSZ;
        float gx = (Ic[y*WW+xp]-Ic[y*WW+xm])*0.5f;
        float gy = (Ic[yp*WW+x]-Ic[ym*WW+x])*0.5f;
        g_pack[(b*CC+c)*HWSZ + pix] = make_float4(Ic[pix], gx, gy, 0.0f);
    }
}

// float 6x6 solve + se3 exp + pose update, run by one thread
__device__ void solve_batch(int b, float* __restrict__ out, int write_out) {
    double* a = g_acc + b*27;
    float M[6][7];
    {
        int k=6;
        for (int i=0;i<6;i++)
            for (int j=i;j<6;j++){ float v=(float)a[k]; M[i][j]=v; M[j][i]=v; k++; }
        for (int i=0;i<6;i++){ M[i][i] += 1e-6f; M[i][6] = (float)a[i]; }
    }
    for (int col=0; col<6; col++){
        int piv=col; float best=fabsf(M[col][col]);
        for (int r2=col+1;r2<6;r2++){ float vv=fabsf(M[r2][col]); if (vv>best){best=vv;piv=r2;} }
        if (piv!=col)
            for (int j=0;j<7;j++){ float tmp=M[col][j]; M[col][j]=M[piv][j]; M[piv][j]=tmp; }
        float ip = 1.0f/M[col][col];
        for (int r2=col+1;r2<6;r2++){
            float f = M[r2][col]*ip;
            for (int j=col;j<7;j++) M[r2][j] -= f*M[col][j];
        }
    }
    float xi[6];
    for (int i=5;i>=0;i--){
        float s = M[i][6];
        for (int j=i+1;j<6;j++) s -= M[i][j]*xi[j];
        xi[i] = s/M[i][i];
    }

    float w0=xi[0],w1=xi[1],w2=xi[2],v0=xi[3],v1=xi[4],v2=xi[5];
    float th2 = w0*w0+w1*w1+w2*w2;
    float A,Bc,Cc;
    if (th2 < 1e-8f){
        A = 1.0f - th2/6.0f; Bc = 0.5f - th2/24.0f; Cc = 1.0f/6.0f - th2/120.0f;
    } else {
        float th = sqrtf(th2);
        float s, cth;
        sincosf(th, &s, &cth);
        A = s/th; Bc = (1.0f-cth)/th2; Cc = (th-s)/(th2*th);
    }
    float K[3][3] = {{0.f,-w2,w1},{w2,0.f,-w0},{-w1,w0,0.f}};
    float K2[3][3];
    for (int i=0;i<3;i++)
        for (int j=0;j<3;j++)
            K2[i][j] = K[i][0]*K[0][j]+K[i][1]*K[1][j]+K[i][2]*K[2][j];
    float T[4][4];
    float Vm[3][3];
    for (int i=0;i<3;i++)
        for (int j=0;j<3;j++){
            float I = (i==j)?1.0f:0.0f;
            T[i][j]  = I + A*K[i][j] + Bc*K2[i][j];
            Vm[i][j] = I + Bc*K[i][j] + Cc*K2[i][j];
        }
    T[0][3] = Vm[0][0]*v0+Vm[0][1]*v1+Vm[0][2]*v2;
    T[1][3] = Vm[1][0]*v0+Vm[1][1]*v1+Vm[1][2]*v2;
    T[2][3] = Vm[2][0]*v0+Vm[2][1]*v1+Vm[2][2]*v2;
    T[3][0]=0.0f; T[3][1]=0.0f; T[3][2]=0.0f; T[3][3]=1.0f;

    float* Pg = g_pose + b*16;
    float Pold[4][4];
    for (int i=0;i<4;i++)
        for (int j=0;j<4;j++) Pold[i][j] = Pg[i*4+j];
    float Pn[4][4];
    for (int i=0;i<4;i++)
        for (int j=0;j<4;j++){
            float s=0.0f;
            for (int k=0;k<4;k++) s += T[i][k]*Pold[k][j];
            Pn[i][j]=s;
        }
    for (int i=0;i<4;i++)
        for (int j=0;j<4;j++) Pg[i*4+j] = Pn[i][j];

    for (int k=0;k<27;k++) a[k]=0.0;

    if (write_out){
        for (int i=0;i<4;i++)
            for (int j=0;j<4;j++)
                out[b*16 + i*4 + j] = Pn[i][j];
    }
}

__global__ void __launch_bounds__(256,3) accumsolve_kernel(
    const float* __restrict__ I1, const float* __restrict__ depth1,
    const float* __restrict__ intr, float* __restrict__ out, int write_out)
{
    int tid  = threadIdx.x;
    int lpix = tid & (PIXPB-1);
    int cg   = tid >> 7;                 // channel group: 0 -> ch 0..3 + ICP, 1 -> ch 4..7
    int pix  = blockIdx.x*PIXPB + lpix;
    int b    = blockIdx.y;

    const float* P = g_pose + b*16;
    float R00=P[0],  R01=P[1],  R02=P[2],  t0=P[3];
    float R10=P[4],  R11=P[5],  R12=P[6],  t1=P[7];
    float R20=P[8],  R21=P[9],  R22=P[10], t2=P[11];

    int x = pix & (WW-1), y = pix / WW;
    float fx = intr[b*4+0], fy = intr[b*4+1], cx = intr[b*4+2], cy = intr[b*4+3];

    float d1 = depth1[b*HWSZ+pix];
    float4 icpc = g_icp[b*HWSZ+pix];
    float d0c = icpc.w;

    float Vx = ((float)x-cx)/fx*d1;
    float Vy = ((float)y-cy)/fy*d1;
    float Vz = d1;

    float Xx = R00*Vx+R01*Vy+R02*Vz+t0;
    float Xy = R10*Vx+R11*Vy+R12*Vz+t1;
    float Xz = R20*Vx+R21*Vy+R22*Vz+t2;

    bool  valid0 = Xz > 1e-8f;
    float zs = (fabsf(Xz) > 1e-8f) ? Xz : 1e-8f;
    float iz = __fdividef(1.0f, zs);
    float u = fx*Xx*iz + cx;
    float v = fy*Xy*iz + cy;

    bool valid = (u>0.0f) && (u<(float)(WW-1)) && (v>0.0f) && (v<(float)(HH-1))
               && valid0 && (d0c>0.0f) && (d1>0.0f);
    float vmask = valid ? 1.0f : 0.0f;

    // branchless clamped bilinear setup
    int iu = min(max((int)floorf(u), 0), WW-2);
    int iv = min(max((int)floorf(v), 0), HH-2);
    float du = fminf(fmaxf(u - (float)iu, 0.0f), 1.0f);
    float dv = fminf(fmaxf(v - (float)iv, 0.0f), 1.0f);
    float w00=(1.0f-du)*(1.0f-dv)*vmask, w10=du*(1.0f-dv)*vmask;
    float w01=(1.0f-du)*dv*vmask,        w11=du*dv*vmask;
    int i00 = iv*WW+iu;

    float a  = Xx*iz, bq = Xy*iz;
    float fxz = fx*iz, fyz = fy*iz;
    // A = row0 of Jw (A[4]=0), B = row1 of Jw (B[3]=0)
    float Av[6] = { -fx*a*bq,         fx*(1.0f+a*a), -fx*bq, fxz, 0.0f, -fxz*a };
    float Bv[6] = { -fy*(1.0f+bq*bq), fy*a*bq,        fy*a,  0.0f, fyz, -fyz*bq };

    // front-load the 4 coalesced I1 reads for this channel group
    const float*  i1b = I1 + (size_t)(b*CC + cg*4)*HWSZ;
    float i1v[4];
    #pragma unroll
    for (int c=0;c<4;c++) i1v[c] = i1b[(size_t)c*HWSZ + pix];

    // ---- photometric channels (4 per group): rank-2 sufficient statistics ----
    float Sxx=0.f, Sxy=0.f, Syy=0.f, Srx=0.f, Sry=0.f;
    {
        const float4* pk = g_pack + (size_t)(b*CC + cg*4)*HWSZ;
        #pragma unroll
        for (int c=0;c<4;c++){
            const float4* p = pk + (size_t)c*HWSZ;
            float4 q00 = p[i00];
            float4 q10 = p[i00+1];
            float4 q01 = p[i00+WW];
            float4 q11 = p[i00+WW+1];
            float s  = w00*q00.x + w10*q10.x + w01*q01.x + w11*q11.x;
            float gx = w00*q00.y + w10*q10.y + w01*q01.y + w11*q11.y;
            float gy = w00*q00.z + w10*q10.z + w01*q01.z + w11*q11.z;
            float r = i1v[c] - s;
            float ar = fabsf(r);
            float w  = (ar <= 0.5f) ? 1.0f : __fdividef(0.5f, fmaxf(ar, 1e-12f));
            Sxx += w*gx*gx;
            Sxy += w*gx*gy;
            Syy += w*gy*gy;
            Srx += w*r*gx;
            Sry += w*r*gy;
        }
    }

    float acc[27];
    {
        #pragma unroll
        for (int i=0;i<6;i++) acc[i] = Srx*Av[i] + Sry*Bv[i];
        int k=6;
        #pragma unroll
        for (int i=0;i<6;i++){
            float xA = Sxx*Av[i] + Sxy*Bv[i];
            float xB = Sxy*Av[i] + Syy*Bv[i];
            #pragma unroll
            for (int j=i;j<6;j++){
                acc[k] = xA*Av[j] + xB*Bv[j];
                k++;
            }
        }
    }

    // ---- ICP channel (group 0 only; warp-uniform branch) ----
    if (cg == 0) {
        const float4* ip = g_icp + b*HWSZ;
        float4 e00 = ip[i00];
        float4 e10 = ip[i00+1];
        float4 e01 = ip[i00+WW];
        float4 e11 = ip[i00+WW+1];

        float pxl = ((float)iu    -cx)/fx, pxr = ((float)(iu+1)-cx)/fx;
        float pyt = ((float)iv    -cy)/fy, pyb = ((float)(iv+1)-cy)/fy;
        float rVx = w00*pxl*e00.w + w10*pxr*e10.w + w01*pxl*e01.w + w11*pxr*e11.w;
        float rVy = w00*pyt*e00.w + w10*pyt*e10.w + w01*pyb*e01.w + w11*pyb*e11.w;
        float rVz = w00*e00.w + w10*e10.w + w01*e01.w + w11*e11.w;

        float rNx = w00*e00.x + w10*e10.x + w01*e01.x + w11*e11.x;
        float rNy = w00*e00.y + w10*e10.y + w01*e01.y + w11*e11.y;
        float rNz = w00*e00.z + w10*e10.z + w01*e01.z + w11*e11.z;

        float dfx = Xx - rVx, dfy = Xy - rVy, dfz = Xz - rVz;
        float dn2 = dfx*dfx+dfy*dfy+dfz*dfz + 1e-12f;
        bool occ = dn2 > 0.01f;    // dn>0.1  (inviews == inb for contributing pixels)

        float nR0 = rNx*R00 + rNy*R10 + rNz*R20;
        float nR1 = rNx*R01 + rNy*R11 + rNz*R21;
        float nR2 = rNx*R02 + rNy*R12 + rNz*R22;

        float res = rNx*dfx + rNy*dfy + rNz*dfz;

        float sd0 = d1 * (5.5f/525.0f);
        float sd2 = d1*d1 * (0.4f/(525.0f*1.2f));
        float cov = (nR0*nR0 + nR1*nR1)*sd0*sd0 + nR2*nR2*sd2*sd2;
        float sigma = sqrtf(cov + 1e-8f);
        float isig = __fdividef(1.0f, sigma + 1e-8f);

        res *= isig;
        if (occ) res = 1e-6f;

        float Jr0 = nR1*Vz - nR2*Vy;
        float Jr1 = nR2*Vx - nR0*Vz;
        float Jr2 = nR0*Vy - nR1*Vx;
        float gis = GEOMW*isig;
        float J[6] = { -Jr0*gis, -Jr1*gis, -Jr2*gis, nR0*gis, nR1*gis, nR2*gis };
        float r = -GEOMW * res;
        float ar = fabsf(r);
        float w  = (ar <= 0.5f) ? 1.0f : __fdividef(0.5f, fmaxf(ar, 1e-12f));
        float wr = w*r;
        #pragma unroll
        for (int i=0;i<6;i++) acc[i] += J[i]*wr;
        int k=6;
        #pragma unroll
        for (int i=0;i<6;i++){
            float wJi = w*J[i];
            #pragma unroll
            for (int j=i;j<6;j++){
                acc[k] += wJi*J[j];
                k++;
            }
        }
    }

    // ---- reduction: float warp shuffles -> shared double -> global atomics ----
    __shared__ double sred[27];
    __shared__ bool amLast;
    if (tid < 27) sred[tid] = 0.0;
    __syncthreads();
    #pragma unroll
    for (int k=0;k<27;k++){
        float val = acc[k];
        #pragma unroll
        for (int off=16;off>0;off>>=1)
            val += __shfl_down_sync(0xffffffffu, val, off);
        if ((tid & 31) == 0) atomicAdd(&sred[k], (double)val);
    }
    __syncthreads();
    if (tid < 27) atomicAdd(&g_acc[b*27+tid], sred[tid]);

    // ---- last block for this batch performs the solve ----
    __threadfence();
    __syncthreads();
    if (tid == 0){
        int prev = atomicAdd(&g_cnt[b], 1);
        amLast = (prev == NBLKX-1);
    }
    __syncthreads();
    if (amLast && tid == 0){
        __threadfence();
        solve_batch(b, out, write_out);
        g_cnt[b] = 0;
    }
}

extern "C" void kernel_launch(void* const* d_in, const int* in_sizes, int n_in,
                              void* d_out, int out_size) {
    const float* pose   = (const float*)d_in[0];
    const float* I0     = (const float*)d_in[1];
    const float* I1     = (const float*)d_in[2];
    const float* intr   = (const float*)d_in[5];
    const float* depth0 = (const float*)d_in[6];
    const float* depth1 = (const float*)d_in[7];
    (void)in_sizes; (void)n_in; (void)out_size;

    dim3 pgrid(HWSZ/256, BB);
    precompute_kernel<<<pgrid,256>>>(I0, depth0, intr, pose);
    dim3 agrid(NBLKX, BB);
    for (int it=0; it<3; it++){
        accumsolve_kernel<<<agrid,256>>>(I1, depth1, intr, (float*)d_out, (it==2) ? 1 : 0);
    }
}

// round 9
// speedup vs baseline: 2.4879x; 1.7354x over previous
#include <cuda_runtime.h>
#include <math.h>

#define BB 4
#define CC 8
#define HH 192
#define WW 256
#define HWSZ (HH*WW)
#define GEOMW 0.01f
#define PIXPB 128                 // pixels per block (x2 channel groups = 256 threads)
#define NBLKX (HWSZ/PIXPB)        // 384 blocks per batch

// Static device scratch (no allocations allowed)
__device__ float4 g_pack[BB*CC*HWSZ];   // {I0, dIx, dIy, 0}, layout [b][c][pix]
__device__ float4 g_icp [BB*HWSZ];      // {nx, ny, nz, depth0}, layout [b][pix]
__device__ float  g_pose[BB*16];
__device__ double g_acc [BB*27];
__device__ int    g_cnt [BB];

__global__ void __launch_bounds__(256) precompute_kernel(
    const float* __restrict__ I0, const float* __restrict__ depth0,
    const float* __restrict__ intr, const float* __restrict__ pose_in)
{
    int pix = blockIdx.x*256 + threadIdx.x;
    int b = blockIdx.y;

    if (blockIdx.x == 0 && b == 0) {
        int i = threadIdx.x;
        if (i < BB*16) g_pose[i] = pose_in[i];
        if (i < BB*27) g_acc[i]  = 0.0;
        if (i < BB)    g_cnt[i]  = 0;
    }

    int x = pix & (WW-1);
    int y = pix / WW;
    float fx = intr[b*4+0], fy = intr[b*4+1], cx = intr[b*4+2], cy = intr[b*4+3];
    const float* d0 = depth0 + b*HWSZ;
    int xm = (x>0)? x-1 : 0, xp = (x<WW-1)? x+1 : WW-1;
    int ym = (y>0)? y-1 : 0, yp = (y<HH-1)? y+1 : HH-1;

    float dxm = d0[y*WW+xm], dxp = d0[y*WW+xp];
    float dym = d0[ym*WW+x], dyp = d0[yp*WW+x];
    float dc  = d0[pix];

    float vxm0=((float)xm-cx)/fx*dxm, vxm1=((float)y -cy)/fy*dxm, vxm2=dxm;
    float vxp0=((float)xp-cx)/fx*dxp, vxp1=((float)y -cy)/fy*dxp, vxp2=dxp;
    float vym0=((float)x -cx)/fx*dym, vym1=((float)ym-cy)/fy*dym, vym2=dym;
    float vyp0=((float)x -cx)/fx*dyp, vyp1=((float)yp-cy)/fy*dyp, vyp2=dyp;

    float ax=(vxp0-vxm0)*0.5f, ay=(vxp1-vxm1)*0.5f, az=(vxp2-vxm2)*0.5f;
    float bx=(vyp0-vym0)*0.5f, by=(vyp1-vym1)*0.5f, bz=(vyp2-vym2)*0.5f;

    float nx = ay*bz - az*by;
    float ny = az*bx - ax*bz;
    float nz = ax*by - ay*bx;
    float inv = 1.0f/sqrtf(nx*nx+ny*ny+nz*nz + 1e-12f);
    g_icp[b*HWSZ + pix] = make_float4(nx*inv, ny*inv, nz*inv, dc);

    #pragma unroll
    for (int c=0;c<CC;c++){
        const float* Ic = I0 + (size_t)(b*CC+c)*HWSZ;
        float gx = (Ic[y*WW+xp]-Ic[y*WW+xm])*0.5f;
        float gy = (Ic[yp*WW+x]-Ic[ym*WW+x])*0.5f;
        g_pack[(b*CC+c)*HWSZ + pix] = make_float4(Ic[pix], gx, gy, 0.0f);
    }
}

// float 6x6 solve + se3 exp + pose update, run by one thread
__device__ void solve_batch(int b, float* __restrict__ out, int write_out) {
    double* a = g_acc + b*27;
    float M[6][7];
    {
        int k=6;
        for (int i=0;i<6;i++)
            for (int j=i;j<6;j++){ float v=(float)a[k]; M[i][j]=v; M[j][i]=v; k++; }
        for (int i=0;i<6;i++){ M[i][i] += 1e-6f; M[i][6] = (float)a[i]; }
    }
    for (int col=0; col<6; col++){
        int piv=col; float best=fabsf(M[col][col]);
        for (int r2=col+1;r2<6;r2++){ float vv=fabsf(M[r2][col]); if (vv>best){best=vv;piv=r2;} }
        if (piv!=col)
            for (int j=0;j<7;j++){ float tmp=M[col][j]; M[col][j]=M[piv][j]; M[piv][j]=tmp; }
        float ip = 1.0f/M[col][col];
        for (int r2=col+1;r2<6;r2++){
            float f = M[r2][col]*ip;
            for (int j=col;j<7;j++) M[r2][j] -= f*M[col][j];
        }
    }
    float xi[6];
    for (int i=5;i>=0;i--){
        float s = M[i][6];
        for (int j=i+1;j<6;j++) s -= M[i][j]*xi[j];
        xi[i] = s/M[i][i];
    }

    float w0=xi[0],w1=xi[1],w2=xi[2],v0=xi[3],v1=xi[4],v2=xi[5];
    float th2 = w0*w0+w1*w1+w2*w2;
    float A,Bc,Cc;
    if (th2 < 1e-8f){
        A = 1.0f - th2/6.0f; Bc = 0.5f - th2/24.0f; Cc = 1.0f/6.0f - th2/120.0f;
    } else {
        float th = sqrtf(th2);
        float s, cth;
        sincosf(th, &s, &cth);
        A = s/th; Bc = (1.0f-cth)/th2; Cc = (th-s)/(th2*th);
    }
    float K[3][3] = {{0.f,-w2,w1},{w2,0.f,-w0},{-w1,w0,0.f}};
    float K2[3][3];
    for (int i=0;i<3;i++)
        for (int j=0;j<3;j++)
            K2[i][j] = K[i][0]*K[0][j]+K[i][1]*K[1][j]+K[i][2]*K[2][j];
    float T[4][4];
    float Vm[3][3];
    for (int i=0;i<3;i++)
        for (int j=0;j<3;j++){
            float I = (i==j)?1.0f:0.0f;
            T[i][j]  = I + A*K[i][j] + Bc*K2[i][j];
            Vm[i][j] = I + Bc*K[i][j] + Cc*K2[i][j];
        }
    T[0][3] = Vm[0][0]*v0+Vm[0][1]*v1+Vm[0][2]*v2;
    T[1][3] = Vm[1][0]*v0+Vm[1][1]*v1+Vm[1][2]*v2;
    T[2][3] = Vm[2][0]*v0+Vm[2][1]*v1+Vm[2][2]*v2;
    T[3][0]=0.0f; T[3][1]=0.0f; T[3][2]=0.0f; T[3][3]=1.0f;

    float* Pg = g_pose + b*16;
    float Pold[4][4];
    for (int i=0;i<4;i++)
        for (int j=0;j<4;j++) Pold[i][j] = Pg[i*4+j];
    float Pn[4][4];
    for (int i=0;i<4;i++)
        for (int j=0;j<4;j++){
            float s=0.0f;
            for (int k=0;k<4;k++) s += T[i][k]*Pold[k][j];
            Pn[i][j]=s;
        }
    for (int i=0;i<4;i++)
        for (int j=0;j<4;j++) Pg[i*4+j] = Pn[i][j];

    for (int k=0;k<27;k++) a[k]=0.0;

    if (write_out){
        for (int i=0;i<4;i++)
            for (int j=0;j<4;j++)
                out[b*16 + i*4 + j] = Pn[i][j];
    }
}

__global__ void __launch_bounds__(256,4) accumsolve_kernel(
    const float* __restrict__ I1, const float* __restrict__ depth1,
    const float* __restrict__ intr, float* __restrict__ out, int write_out)
{
    int tid  = threadIdx.x;
    int lpix = tid & (PIXPB-1);
    int cg   = tid >> 7;                 // channel group: 0 -> ch 0..3 + ICP, 1 -> ch 4..7
    int pix  = blockIdx.x*PIXPB + lpix;
    int b    = blockIdx.y;

    const float* P = g_pose + b*16;
    float R00=P[0],  R01=P[1],  R02=P[2],  t0=P[3];
    float R10=P[4],  R11=P[5],  R12=P[6],  t1=P[7];
    float R20=P[8],  R21=P[9],  R22=P[10], t2=P[11];

    int x = pix & (WW-1), y = pix / WW;
    float fx = intr[b*4+0], fy = intr[b*4+1], cx = intr[b*4+2], cy = intr[b*4+3];

    float d1 = depth1[b*HWSZ+pix];
    float4 icpc = g_icp[b*HWSZ+pix];
    float d0c = icpc.w;

    float Vx = ((float)x-cx)/fx*d1;
    float Vy = ((float)y-cy)/fy*d1;
    float Vz = d1;

    float Xx = R00*Vx+R01*Vy+R02*Vz+t0;
    float Xy = R10*Vx+R11*Vy+R12*Vz+t1;
    float Xz = R20*Vx+R21*Vy+R22*Vz+t2;

    bool  valid0 = Xz > 1e-8f;
    float zs = (fabsf(Xz) > 1e-8f) ? Xz : 1e-8f;
    float iz = __fdividef(1.0f, zs);
    float u = fx*Xx*iz + cx;
    float v = fy*Xy*iz + cy;

    bool valid = (u>0.0f) && (u<(float)(WW-1)) && (v>0.0f) && (v<(float)(HH-1))
               && valid0 && (d0c>0.0f) && (d1>0.0f);
    float vmask = valid ? 1.0f : 0.0f;

    // branchless clamped bilinear setup
    int iu = min(max((int)floorf(u), 0), WW-2);
    int iv = min(max((int)floorf(v), 0), HH-2);
    float du = fminf(fmaxf(u - (float)iu, 0.0f), 1.0f);
    float dv = fminf(fmaxf(v - (float)iv, 0.0f), 1.0f);
    float w00=(1.0f-du)*(1.0f-dv)*vmask, w10=du*(1.0f-dv)*vmask;
    float w01=(1.0f-du)*dv*vmask,        w11=du*dv*vmask;
    int i00 = iv*WW+iu;

    float a  = Xx*iz, bq = Xy*iz;
    float fxz = fx*iz, fyz = fy*iz;
    // A = row0 of Jw (A[4]=0), B = row1 of Jw (B[3]=0)
    float Av[6] = { -fx*a*bq,         fx*(1.0f+a*a), -fx*bq, fxz, 0.0f, -fxz*a };
    float Bv[6] = { -fy*(1.0f+bq*bq), fy*a*bq,        fy*a,  0.0f, fyz, -fyz*bq };

    // front-load the 4 coalesced I1 reads for this channel group
    const float*  i1b = I1 + (size_t)(b*CC + cg*4)*HWSZ;
    float i1v[4];
    #pragma unroll
    for (int c=0;c<4;c++) i1v[c] = i1b[(size_t)c*HWSZ + pix];

    // ---- photometric channels (4 per group): rank-2 sufficient statistics ----
    float Sxx=0.f, Sxy=0.f, Syy=0.f, Srx=0.f, Sry=0.f;
    {
        const float4* pk = g_pack + (size_t)(b*CC + cg*4)*HWSZ;
        #pragma unroll
        for (int c=0;c<4;c++){
            const float4* p = pk + (size_t)c*HWSZ;
            float4 q00 = p[i00];
            float4 q10 = p[i00+1];
            float4 q01 = p[i00+WW];
            float4 q11 = p[i00+WW+1];
            float s  = w00*q00.x + w10*q10.x + w01*q01.x + w11*q11.x;
            float gx = w00*q00.y + w10*q10.y + w01*q01.y + w11*q11.y;
            float gy = w00*q00.z + w10*q10.z + w01*q01.z + w11*q11.z;
            float r = i1v[c] - s;
            float ar = fabsf(r);
            float w  = (ar <= 0.5f) ? 1.0f : __fdividef(0.5f, fmaxf(ar, 1e-12f));
            Sxx += w*gx*gx;
            Sxy += w*gx*gy;
            Syy += w*gy*gy;
            Srx += w*r*gx;
            Sry += w*r*gy;
        }
    }

    float acc[27];
    {
        #pragma unroll
        for (int i=0;i<6;i++) acc[i] = Srx*Av[i] + Sry*Bv[i];
        int k=6;
        #pragma unroll
        for (int i=0;i<6;i++){
            float xA = Sxx*Av[i] + Sxy*Bv[i];
            float xB = Sxy*Av[i] + Syy*Bv[i];
            #pragma unroll
            for (int j=i;j<6;j++){
                acc[k] = xA*Av[j] + xB*Bv[j];
                k++;
            }
        }
    }

    // ---- ICP channel (group 0 only; warp-uniform branch) ----
    if (cg == 0) {
        const float4* ip = g_icp + b*HWSZ;
        float4 e00 = ip[i00];
        float4 e10 = ip[i00+1];
        float4 e01 = ip[i00+WW];
        float4 e11 = ip[i00+WW+1];

        float pxl = ((float)iu    -cx)/fx, pxr = ((float)(iu+1)-cx)/fx;
        float pyt = ((float)iv    -cy)/fy, pyb = ((float)(iv+1)-cy)/fy;
        float rVx = w00*pxl*e00.w + w10*pxr*e10.w + w01*pxl*e01.w + w11*pxr*e11.w;
        float rVy = w00*pyt*e00.w + w10*pyt*e10.w + w01*pyb*e01.w + w11*pyb*e11.w;
        float rVz = w00*e00.w + w10*e10.w + w01*e01.w + w11*e11.w;

        float rNx = w00*e00.x + w10*e10.x + w01*e01.x + w11*e11.x;
        float rNy = w00*e00.y + w10*e10.y + w01*e01.y + w11*e11.y;
        float rNz = w00*e00.z + w10*e10.z + w01*e01.z + w11*e11.z;

        float dfx = Xx - rVx, dfy = Xy - rVy, dfz = Xz - rVz;
        float dn2 = dfx*dfx+dfy*dfy+dfz*dfz + 1e-12f;
        bool occ = dn2 > 0.01f;    // dn>0.1  (inviews == inb for contributing pixels)

        float nR0 = rNx*R00 + rNy*R10 + rNz*R20;
        float nR1 = rNx*R01 + rNy*R11 + rNz*R21;
        float nR2 = rNx*R02 + rNy*R12 + rNz*R22;

        float res = rNx*dfx + rNy*dfy + rNz*dfz;

        float sd0 = d1 * (5.5f/525.0f);
        float sd2 = d1*d1 * (0.4f/(525.0f*1.2f));
        float cov = (nR0*nR0 + nR1*nR1)*sd0*sd0 + nR2*nR2*sd2*sd2;
        float sigma = sqrtf(cov + 1e-8f);
        float isig = __fdividef(1.0f, sigma + 1e-8f);

        res *= isig;
        if (occ) res = 1e-6f;

        float Jr0 = nR1*Vz - nR2*Vy;
        float Jr1 = nR2*Vx - nR0*Vz;
        float Jr2 = nR0*Vy - nR1*Vx;
        float gis = GEOMW*isig;
        float J[6] = { -Jr0*gis, -Jr1*gis, -Jr2*gis, nR0*gis, nR1*gis, nR2*gis };
        float r = -GEOMW * res;
        float ar = fabsf(r);
        float w  = (ar <= 0.5f) ? 1.0f : __fdividef(0.5f, fmaxf(ar, 1e-12f));
        float wr = w*r;
        #pragma unroll
        for (int i=0;i<6;i++) acc[i] += J[i]*wr;
        int k=6;
        #pragma unroll
        for (int i=0;i<6;i++){
            float wJi = w*J[i];
            #pragma unroll
            for (int j=i;j<6;j++){
                acc[k] += wJi*J[j];
                k++;
            }
        }
    }

    // ---- reduction: 4-level shuffles (16-lane halves) -> shared float atomics
    //      -> one double atomic per value per block ----
    __shared__ float  sredf[27];
    __shared__ bool amLast;
    if (tid < 27) sredf[tid] = 0.0f;
    __syncthreads();
    #pragma unroll
    for (int k=0;k<27;k++){
        float val = acc[k];
        val += __shfl_down_sync(0xffffffffu, val, 8);
        val += __shfl_down_sync(0xffffffffu, val, 4);
        val += __shfl_down_sync(0xffffffffu, val, 2);
        val += __shfl_down_sync(0xffffffffu, val, 1);
        if ((tid & 15) == 0) atomicAdd(&sredf[k], val);  // lanes 0 and 16
    }
    __syncthreads();
    if (tid < 27) atomicAdd(&g_acc[b*27+tid], (double)sredf[tid]);

    // ---- last block for this batch performs the solve ----
    __threadfence();
    __syncthreads();
    if (tid == 0){
        int prev = atomicAdd(&g_cnt[b], 1);
        amLast = (prev == NBLKX-1);
    }
    __syncthreads();
    if (amLast && tid == 0){
        __threadfence();
        solve_batch(b, out, write_out);
        g_cnt[b] = 0;
    }
}

extern "C" void kernel_launch(void* const* d_in, const int* in_sizes, int n_in,
                              void* d_out, int out_size) {
    const float* pose   = (const float*)d_in[0];
    const float* I0     = (const float*)d_in[1];
    const float* I1     = (const float*)d_in[2];
    const float* intr   = (const float*)d_in[5];
    const float* depth0 = (const float*)d_in[6];
    const float* depth1 = (const float*)d_in[7];
    (void)in_sizes; (void)n_in; (void)out_size;

    dim3 pgrid(HWSZ/256, BB);
    precompute_kernel<<<pgrid,256>>>(I0, depth0, intr, pose);
    dim3 agrid(NBLKX, BB);
    for (int it=0; it<3; it++){
        accumsolve_kernel<<<agrid,256>>>(I1, depth1, intr, (float*)d_out, (it==2) ? 1 : 0);
    }
}

// round 10
// speedup vs baseline: 2.6550x; 1.0672x over previous
#include <cuda_runtime.h>
#include <cuda_fp16.h>
#include <math.h>

#define BB 4
#define CC 8
#define HH 192
#define WW 256
#define HWSZ (HH*WW)
#define GEOMW 0.01f
#define PIXPB 128                 // pixels per block (x2 channel groups = 256 threads)
#define NBLKX (HWSZ/PIXPB)        // 384 blocks per batch

// Static device scratch (no allocations allowed)
// photometric pack: [b][cg][pix] -> 32 bytes = 4 channels x {I0,gx,gy,pad} fp16
__device__ uint4  g_packh[BB*2*HWSZ*2];
__device__ float4 g_icp  [BB*HWSZ];     // {nx, ny, nz, depth0}, layout [b][pix]
__device__ float  g_pose[BB*16];
__device__ double g_acc [BB*27];
__device__ int    g_cnt [BB];

__global__ void __launch_bounds__(256) precompute_kernel(
    const float* __restrict__ I0, const float* __restrict__ depth0,
    const float* __restrict__ intr, const float* __restrict__ pose_in)
{
    int pix = blockIdx.x*256 + threadIdx.x;
    int b = blockIdx.y;

    if (blockIdx.x == 0 && b == 0) {
        int i = threadIdx.x;
        if (i < BB*16) g_pose[i] = pose_in[i];
        if (i < BB*27) g_acc[i]  = 0.0;
        if (i < BB)    g_cnt[i]  = 0;
    }

    int x = pix & (WW-1);
    int y = pix / WW;
    float fx = intr[b*4+0], fy = intr[b*4+1], cx = intr[b*4+2], cy = intr[b*4+3];
    const float* d0 = depth0 + b*HWSZ;
    int xm = (x>0)? x-1 : 0, xp = (x<WW-1)? x+1 : WW-1;
    int ym = (y>0)? y-1 : 0, yp = (y<HH-1)? y+1 : HH-1;

    float dxm = d0[y*WW+xm], dxp = d0[y*WW+xp];
    float dym = d0[ym*WW+x], dyp = d0[yp*WW+x];
    float dc  = d0[pix];

    float vxm0=((float)xm-cx)/fx*dxm, vxm1=((float)y -cy)/fy*dxm, vxm2=dxm;
    float vxp0=((float)xp-cx)/fx*dxp, vxp1=((float)y -cy)/fy*dxp, vxp2=dxp;
    float vym0=((float)x -cx)/fx*dym, vym1=((float)ym-cy)/fy*dym, vym2=dym;
    float vyp0=((float)x -cx)/fx*dyp, vyp1=((float)yp-cy)/fy*dyp, vyp2=dyp;

    float ax=(vxp0-vxm0)*0.5f, ay=(vxp1-vxm1)*0.5f, az=(vxp2-vxm2)*0.5f;
    float bx=(vyp0-vym0)*0.5f, by=(vyp1-vym1)*0.5f, bz=(vyp2-vym2)*0.5f;

    float nx = ay*bz - az*by;
    float ny = az*bx - ax*bz;
    float nz = ax*by - ay*bx;
    float inv = 1.0f/sqrtf(nx*nx+ny*ny+nz*nz + 1e-12f);
    g_icp[b*HWSZ + pix] = make_float4(nx*inv, ny*inv, nz*inv, dc);

    __half hbuf[2][16];
    #pragma unroll
    for (int c=0;c<CC;c++){
        const float* Ic = I0 + (size_t)(b*CC+c)*HWSZ;
        float gx = (Ic[y*WW+xp]-Ic[y*WW+xm])*0.5f;
        float gy = (Ic[yp*WW+x]-Ic[ym*WW+x])*0.5f;
        int cg = c >> 2, idx = (c & 3)*4;
        hbuf[cg][idx+0] = __float2half_rn(Ic[pix]);
        hbuf[cg][idx+1] = __float2half_rn(gx);
        hbuf[cg][idx+2] = __float2half_rn(gy);
        hbuf[cg][idx+3] = __float2half_rn(0.0f);
    }
    #pragma unroll
    for (int cg=0;cg<2;cg++){
        const uint4* src = (const uint4*)hbuf[cg];
        size_t base = ((size_t)(b*2+cg)*HWSZ + pix)*2;
        g_packh[base+0] = src[0];
        g_packh[base+1] = src[1];
    }
}

// float 6x6 solve + se3 exp + pose update, run by one thread
__device__ void solve_batch(int b, float* __restrict__ out, int write_out) {
    double* a = g_acc + b*27;
    float M[6][7];
    {
        int k=6;
        for (int i=0;i<6;i++)
            for (int j=i;j<6;j++){ float v=(float)a[k]; M[i][j]=v; M[j][i]=v; k++; }
        for (int i=0;i<6;i++){ M[i][i] += 1e-6f; M[i][6] = (float)a[i]; }
    }
    for (int col=0; col<6; col++){
        int piv=col; float best=fabsf(M[col][col]);
        for (int r2=col+1;r2<6;r2++){ float vv=fabsf(M[r2][col]); if (vv>best){best=vv;piv=r2;} }
        if (piv!=col)
            for (int j=0;j<7;j++){ float tmp=M[col][j]; M[col][j]=M[piv][j]; M[piv][j]=tmp; }
        float ip = 1.0f/M[col][col];
        for (int r2=col+1;r2<6;r2++){
            float f = M[r2][col]*ip;
            for (int j=col;j<7;j++) M[r2][j] -= f*M[col][j];
        }
    }
    float xi[6];
    for (int i=5;i>=0;i--){
        float s = M[i][6];
        for (int j=i+1;j<6;j++) s -= M[i][j]*xi[j];
        xi[i] = s/M[i][i];
    }

    float w0=xi[0],w1=xi[1],w2=xi[2],v0=xi[3],v1=xi[4],v2=xi[5];
    float th2 = w0*w0+w1*w1+w2*w2;
    float A,Bc,Cc;
    if (th2 < 1e-8f){
        A = 1.0f - th2/6.0f; Bc = 0.5f - th2/24.0f; Cc = 1.0f/6.0f - th2/120.0f;
    } else {
        float th = sqrtf(th2);
        float s, cth;
        sincosf(th, &s, &cth);
        A = s/th; Bc = (1.0f-cth)/th2; Cc = (th-s)/(th2*th);
    }
    float K[3][3] = {{0.f,-w2,w1},{w2,0.f,-w0},{-w1,w0,0.f}};
    float K2[3][3];
    for (int i=0;i<3;i++)
        for (int j=0;j<3;j++)
            K2[i][j] = K[i][0]*K[0][j]+K[i][1]*K[1][j]+K[i][2]*K[2][j];
    float T[4][4];
    float Vm[3][3];
    for (int i=0;i<3;i++)
        for (int j=0;j<3;j++){
            float I = (i==j)?1.0f:0.0f;
            T[i][j]  = I + A*K[i][j] + Bc*K2[i][j];
            Vm[i][j] = I + Bc*K[i][j] + Cc*K2[i][j];
        }
    T[0][3] = Vm[0][0]*v0+Vm[0][1]*v1+Vm[0][2]*v2;
    T[1][3] = Vm[1][0]*v0+Vm[1][1]*v1+Vm[1][2]*v2;
    T[2][3] = Vm[2][0]*v0+Vm[2][1]*v1+Vm[2][2]*v2;
    T[3][0]=0.0f; T[3][1]=0.0f; T[3][2]=0.0f; T[3][3]=1.0f;

    float* Pg = g_pose + b*16;
    float Pold[4][4];
    for (int i=0;i<4;i++)
        for (int j=0;j<4;j++) Pold[i][j] = Pg[i*4+j];
    float Pn[4][4];
    for (int i=0;i<4;i++)
        for (int j=0;j<4;j++){
            float s=0.0f;
            for (int k=0;k<4;k++) s += T[i][k]*Pold[k][j];
            Pn[i][j]=s;
        }
    for (int i=0;i<4;i++)
        for (int j=0;j<4;j++) Pg[i*4+j] = Pn[i][j];

    for (int k=0;k<27;k++) a[k]=0.0;

    if (write_out){
        for (int i=0;i<4;i++)
            for (int j=0;j<4;j++)
                out[b*16 + i*4 + j] = Pn[i][j];
    }
}

// extract {I0,gx,gy} for channel c (0..3) from the two packed uint4s
__device__ __forceinline__ void get3(const uint4& qa, const uint4& qb, int c,
                                     float& I, float& gx, float& gy) {
    const __half2* h = (c < 2) ? (const __half2*)&qa : (const __half2*)&qb;
    int s = (c & 1) * 2;
    float2 p = __half22float2(h[s]);
    float2 q = __half22float2(h[s+1]);
    I = p.x; gx = p.y; gy = q.x;
}

__global__ void __launch_bounds__(256,4) accumsolve_kernel(
    const float* __restrict__ I1, const float* __restrict__ depth1,
    const float* __restrict__ intr, float* __restrict__ out, int write_out)
{
    int tid  = threadIdx.x;
    int lpix = tid & (PIXPB-1);
    int cg   = tid >> 7;                 // channel group: 0 -> ch 0..3 + ICP, 1 -> ch 4..7
    int pix  = blockIdx.x*PIXPB + lpix;
    int b    = blockIdx.y;

    const float* P = g_pose + b*16;
    float R00=P[0],  R01=P[1],  R02=P[2],  t0=P[3];
    float R10=P[4],  R11=P[5],  R12=P[6],  t1=P[7];
    float R20=P[8],  R21=P[9],  R22=P[10], t2=P[11];

    int x = pix & (WW-1), y = pix / WW;
    float fx = intr[b*4+0], fy = intr[b*4+1], cx = intr[b*4+2], cy = intr[b*4+3];

    float d1 = depth1[b*HWSZ+pix];
    float4 icpc = g_icp[b*HWSZ+pix];
    float d0c = icpc.w;

    float Vx = ((float)x-cx)/fx*d1;
    float Vy = ((float)y-cy)/fy*d1;
    float Vz = d1;

    float Xx = R00*Vx+R01*Vy+R02*Vz+t0;
    float Xy = R10*Vx+R11*Vy+R12*Vz+t1;
    float Xz = R20*Vx+R21*Vy+R22*Vz+t2;

    bool  valid0 = Xz > 1e-8f;
    float zs = (fabsf(Xz) > 1e-8f) ? Xz : 1e-8f;
    float iz = __fdividef(1.0f, zs);
    float u = fx*Xx*iz + cx;
    float v = fy*Xy*iz + cy;

    bool valid = (u>0.0f) && (u<(float)(WW-1)) && (v>0.0f) && (v<(float)(HH-1))
               && valid0 && (d0c>0.0f) && (d1>0.0f);
    float vmask = valid ? 1.0f : 0.0f;

    // branchless clamped bilinear setup
    int iu = min(max((int)floorf(u), 0), WW-2);
    int iv = min(max((int)floorf(v), 0), HH-2);
    float du = fminf(fmaxf(u - (float)iu, 0.0f), 1.0f);
    float dv = fminf(fmaxf(v - (float)iv, 0.0f), 1.0f);
    float w00=(1.0f-du)*(1.0f-dv)*vmask, w10=du*(1.0f-dv)*vmask;
    float w01=(1.0f-du)*dv*vmask,        w11=du*dv*vmask;
    int i00 = iv*WW+iu;

    float a  = Xx*iz, bq = Xy*iz;
    float fxz = fx*iz, fyz = fy*iz;
    // A = row0 of Jw (A[4]=0), B = row1 of Jw (B[3]=0)
    float Av[6] = { -fx*a*bq,         fx*(1.0f+a*a), -fx*bq, fxz, 0.0f, -fxz*a };
    float Bv[6] = { -fy*(1.0f+bq*bq), fy*a*bq,        fy*a,  0.0f, fyz, -fyz*bq };

    // front-load the 4 coalesced I1 reads for this channel group
    const float*  i1b = I1 + (size_t)(b*CC + cg*4)*HWSZ;
    float i1v[4];
    #pragma unroll
    for (int c=0;c<4;c++) i1v[c] = i1b[(size_t)c*HWSZ + pix];

    // ---- photometric: 8 x LDG.128 fetch all 4 channels at 4 corners ----
    const uint4* pk = g_packh + (size_t)(b*2+cg)*HWSZ*2;
    uint4 q00a = pk[(size_t)2*i00],        q00b = pk[(size_t)2*i00+1];
    uint4 q10a = pk[(size_t)2*(i00+1)],    q10b = pk[(size_t)2*(i00+1)+1];
    uint4 q01a = pk[(size_t)2*(i00+WW)],   q01b = pk[(size_t)2*(i00+WW)+1];
    uint4 q11a = pk[(size_t)2*(i00+WW+1)], q11b = pk[(size_t)2*(i00+WW+1)+1];

    float Sxx=0.f, Sxy=0.f, Syy=0.f, Srx=0.f, Sry=0.f;
    #pragma unroll
    for (int c=0;c<4;c++){
        float I00,gx00,gy00, I10,gx10,gy10, I01,gx01,gy01, I11,gx11,gy11;
        get3(q00a,q00b,c, I00,gx00,gy00);
        get3(q10a,q10b,c, I10,gx10,gy10);
        get3(q01a,q01b,c, I01,gx01,gy01);
        get3(q11a,q11b,c, I11,gx11,gy11);
        float s  = w00*I00  + w10*I10  + w01*I01  + w11*I11;
        float gx = w00*gx00 + w10*gx10 + w01*gx01 + w11*gx11;
        float gy = w00*gy00 + w10*gy10 + w01*gy01 + w11*gy11;
        float r = i1v[c] - s;
        float ar = fabsf(r);
        float w  = (ar <= 0.5f) ? 1.0f : __fdividef(0.5f, fmaxf(ar, 1e-12f));
        Sxx += w*gx*gx;
        Sxy += w*gx*gy;
        Syy += w*gy*gy;
        Srx += w*r*gx;
        Sry += w*r*gy;
    }

    float acc[27];
    {
        #pragma unroll
        for (int i=0;i<6;i++) acc[i] = Srx*Av[i] + Sry*Bv[i];
        int k=6;
        #pragma unroll
        for (int i=0;i<6;i++){
            float xA = Sxx*Av[i] + Sxy*Bv[i];
            float xB = Sxy*Av[i] + Syy*Bv[i];
            #pragma unroll
            for (int j=i;j<6;j++){
                acc[k] = xA*Av[j] + xB*Bv[j];
                k++;
            }
        }
    }

    // ---- ICP channel (group 0 only; warp-uniform branch) ----
    if (cg == 0) {
        const float4* ip = g_icp + b*HWSZ;
        float4 e00 = ip[i00];
        float4 e10 = ip[i00+1];
        float4 e01 = ip[i00+WW];
        float4 e11 = ip[i00+WW+1];

        float pxl = ((float)iu    -cx)/fx, pxr = ((float)(iu+1)-cx)/fx;
        float pyt = ((float)iv    -cy)/fy, pyb = ((float)(iv+1)-cy)/fy;
        float rVx = w00*pxl*e00.w + w10*pxr*e10.w + w01*pxl*e01.w + w11*pxr*e11.w;
        float rVy = w00*pyt*e00.w + w10*pyt*e10.w + w01*pyb*e01.w + w11*pyb*e11.w;
        float rVz = w00*e00.w + w10*e10.w + w01*e01.w + w11*e11.w;

        float rNx = w00*e00.x + w10*e10.x + w01*e01.x + w11*e11.x;
        float rNy = w00*e00.y + w10*e10.y + w01*e01.y + w11*e11.y;
        float rNz = w00*e00.z + w10*e10.z + w01*e01.z + w11*e11.z;

        float dfx = Xx - rVx, dfy = Xy - rVy, dfz = Xz - rVz;
        float dn2 = dfx*dfx+dfy*dfy+dfz*dfz + 1e-12f;
        bool occ = dn2 > 0.01f;    // dn>0.1  (inviews == inb for contributing pixels)

        float nR0 = rNx*R00 + rNy*R10 + rNz*R20;
        float nR1 = rNx*R01 + rNy*R11 + rNz*R21;
        float nR2 = rNx*R02 + rNy*R12 + rNz*R22;

        float res = rNx*dfx + rNy*dfy + rNz*dfz;

        float sd0 = d1 * (5.5f/525.0f);
        float sd2 = d1*d1 * (0.4f/(525.0f*1.2f));
        float cov = (nR0*nR0 + nR1*nR1)*sd0*sd0 + nR2*nR2*sd2*sd2;
        float sigma = sqrtf(cov + 1e-8f);
        float isig = __fdividef(1.0f, sigma + 1e-8f);

        res *= isig;
        if (occ) res = 1e-6f;

        float Jr0 = nR1*Vz - nR2*Vy;
        float Jr1 = nR2*Vx - nR0*Vz;
        float Jr2 = nR0*Vy - nR1*Vx;
        float gis = GEOMW*isig;
        float J[6] = { -Jr0*gis, -Jr1*gis, -Jr2*gis, nR0*gis, nR1*gis, nR2*gis };
        float r = -GEOMW * res;
        float ar = fabsf(r);
        float w  = (ar <= 0.5f) ? 1.0f : __fdividef(0.5f, fmaxf(ar, 1e-12f));
        float wr = w*r;
        #pragma unroll
        for (int i=0;i<6;i++) acc[i] += J[i]*wr;
        int k=6;
        #pragma unroll
        for (int i=0;i<6;i++){
            float wJi = w*J[i];
            #pragma unroll
            for (int j=i;j<6;j++){
                acc[k] += wJi*J[j];
                k++;
            }
        }
    }

    // ---- reduction: 4-level shuffles (16-lane halves) -> shared float atomics
    //      -> one double atomic per value per block ----
    __shared__ float  sredf[27];
    __shared__ bool amLast;
    if (tid < 27) sredf[tid] = 0.0f;
    __syncthreads();
    #pragma unroll
    for (int k=0;k<27;k++){
        float val = acc[k];
        val += __shfl_down_sync(0xffffffffu, val, 8);
        val += __shfl_down_sync(0xffffffffu, val, 4);
        val += __shfl_down_sync(0xffffffffu, val, 2);
        val += __shfl_down_sync(0xffffffffu, val, 1);
        if ((tid & 15) == 0) atomicAdd(&sredf[k], val);  // lanes 0 and 16
    }
    __syncthreads();
    if (tid < 27) atomicAdd(&g_acc[b*27+tid], (double)sredf[tid]);

    // ---- last block for this batch performs the solve ----
    __threadfence();
    __syncthreads();
    if (tid == 0){
        int prev = atomicAdd(&g_cnt[b], 1);
        amLast = (prev == NBLKX-1);
    }
    __syncthreads();
    if (amLast && tid == 0){
        __threadfence();
        solve_batch(b, out, write_out);
        g_cnt[b] = 0;
    }
}

extern "C" void kernel_launch(void* const* d_in, const int* in_sizes, int n_in,
                              void* d_out, int out_size) {
    const float* pose   = (const float*)d_in[0];
    const float* I0     = (const float*)d_in[1];
    const float* I1     = (const float*)d_in[2];
    const float* intr   = (const float*)d_in[5];
    const float* depth0 = (const float*)d_in[6];
    const float* depth1 = (const float*)d_in[7];
    (void)in_sizes; (void)n_in; (void)out_size;

    dim3 pgrid(HWSZ/256, BB);
    precompute_kernel<<<pgrid,256>>>(I0, depth0, intr, pose);
    dim3 agrid(NBLKX, BB);
    for (int it=0; it<3; it++){
        accumsolve_kernel<<<agrid,256>>>(I1, depth1, intr, (float*)d_out, (it==2) ? 1 : 0);
    }
}

// round 11
// speedup vs baseline: 4.2748x; 1.6101x over previous
#include <cuda_runtime.h>
#include <cuda_fp16.h>
#include <math.h>

#define BB 4
#define CC 8
#define HH 192
#define WW 256
#define HWSZ (HH*WW)
#define GEOMW 0.01f
#define PIXPB 128                 // pixel lanes per block (x2 channel groups = 256 threads)
#define PPT 4                     // pixels per thread
#define NBLKX (HWSZ/(PIXPB*PPT))  // 96 blocks per batch

// Static device scratch (no allocations allowed)
// photometric pack: [b][cg][pix] -> 32 bytes = 4 channels x {I0,gx,gy,pad} fp16
__device__ uint4  g_packh[BB*2*HWSZ*2];
__device__ float4 g_icp  [BB*HWSZ];     // {nx, ny, nz, depth0}, layout [b][pix]
__device__ float  g_pose[BB*16];
__device__ double g_acc [BB*27];
__device__ int    g_cnt [BB];

__global__ void __launch_bounds__(256) precompute_kernel(
    const float* __restrict__ I0, const float* __restrict__ depth0,
    const float* __restrict__ intr, const float* __restrict__ pose_in)
{
    int pix = blockIdx.x*256 + threadIdx.x;
    int b = blockIdx.y;

    if (blockIdx.x == 0 && b == 0) {
        int i = threadIdx.x;
        if (i < BB*16) g_pose[i] = pose_in[i];
        if (i < BB*27) g_acc[i]  = 0.0;
        if (i < BB)    g_cnt[i]  = 0;
    }

    int x = pix & (WW-1);
    int y = pix / WW;
    float fx = intr[b*4+0], fy = intr[b*4+1], cx = intr[b*4+2], cy = intr[b*4+3];
    const float* d0 = depth0 + b*HWSZ;
    int xm = (x>0)? x-1 : 0, xp = (x<WW-1)? x+1 : WW-1;
    int ym = (y>0)? y-1 : 0, yp = (y<HH-1)? y+1 : HH-1;

    float dxm = d0[y*WW+xm], dxp = d0[y*WW+xp];
    float dym = d0[ym*WW+x], dyp = d0[yp*WW+x];
    float dc  = d0[pix];

    float vxm0=((float)xm-cx)/fx*dxm, vxm1=((float)y -cy)/fy*dxm, vxm2=dxm;
    float vxp0=((float)xp-cx)/fx*dxp, vxp1=((float)y -cy)/fy*dxp, vxp2=dxp;
    float vym0=((float)x -cx)/fx*dym, vym1=((float)ym-cy)/fy*dym, vym2=dym;
    float vyp0=((float)x -cx)/fx*dyp, vyp1=((float)yp-cy)/fy*dyp, vyp2=dyp;

    float ax=(vxp0-vxm0)*0.5f, ay=(vxp1-vxm1)*0.5f, az=(vxp2-vxm2)*0.5f;
    float bx=(vyp0-vym0)*0.5f, by=(vyp1-vym1)*0.5f, bz=(vyp2-vym2)*0.5f;

    float nx = ay*bz - az*by;
    float ny = az*bx - ax*bz;
    float nz = ax*by - ay*bx;
    float inv = 1.0f/sqrtf(nx*nx+ny*ny+nz*nz + 1e-12f);
    g_icp[b*HWSZ + pix] = make_float4(nx*inv, ny*inv, nz*inv, dc);

    __half hbuf[2][16];
    #pragma unroll
    for (int c=0;c<CC;c++){
        const float* Ic = I0 + (size_t)(b*CC+c)*HWSZ;
        float gx = (Ic[y*WW+xp]-Ic[y*WW+xm])*0.5f;
        float gy = (Ic[yp*WW+x]-Ic[ym*WW+x])*0.5f;
        int cg = c >> 2, idx = (c & 3)*4;
        hbuf[cg][idx+0] = __float2half_rn(Ic[pix]);
        hbuf[cg][idx+1] = __float2half_rn(gx);
        hbuf[cg][idx+2] = __float2half_rn(gy);
        hbuf[cg][idx+3] = __float2half_rn(0.0f);
    }
    #pragma unroll
    for (int cg=0;cg<2;cg++){
        const uint4* src = (const uint4*)hbuf[cg];
        size_t base = ((size_t)(b*2+cg)*HWSZ + pix)*2;
        g_packh[base+0] = src[0];
        g_packh[base+1] = src[1];
    }
}

// float 6x6 solve + se3 exp + pose update, run by one thread
__device__ void solve_batch(int b, float* __restrict__ out, int write_out) {
    double* a = g_acc + b*27;
    float M[6][7];
    {
        int k=6;
        for (int i=0;i<6;i++)
            for (int j=i;j<6;j++){ float v=(float)a[k]; M[i][j]=v; M[j][i]=v; k++; }
        for (int i=0;i<6;i++){ M[i][i] += 1e-6f; M[i][6] = (float)a[i]; }
    }
    for (int col=0; col<6; col++){
        int piv=col; float best=fabsf(M[col][col]);
        for (int r2=col+1;r2<6;r2++){ float vv=fabsf(M[r2][col]); if (vv>best){best=vv;piv=r2;} }
        if (piv!=col)
            for (int j=0;j<7;j++){ float tmp=M[col][j]; M[col][j]=M[piv][j]; M[piv][j]=tmp; }
        float ip = 1.0f/M[col][col];
        for (int r2=col+1;r2<6;r2++){
            float f = M[r2][col]*ip;
            for (int j=col;j<7;j++) M[r2][j] -= f*M[col][j];
        }
    }
    float xi[6];
    for (int i=5;i>=0;i--){
        float s = M[i][6];
        for (int j=i+1;j<6;j++) s -= M[i][j]*xi[j];
        xi[i] = s/M[i][i];
    }

    float w0=xi[0],w1=xi[1],w2=xi[2],v0=xi[3],v1=xi[4],v2=xi[5];
    float th2 = w0*w0+w1*w1+w2*w2;
    float A,Bc,Cc;
    if (th2 < 1e-8f){
        A = 1.0f - th2/6.0f; Bc = 0.5f - th2/24.0f; Cc = 1.0f/6.0f - th2/120.0f;
    } else {
        float th = sqrtf(th2);
        float s, cth;
        sincosf(th, &s, &cth);
        A = s/th; Bc = (1.0f-cth)/th2; Cc = (th-s)/(th2*th);
    }
    float K[3][3] = {{0.f,-w2,w1},{w2,0.f,-w0},{-w1,w0,0.f}};
    float K2[3][3];
    for (int i=0;i<3;i++)
        for (int j=0;j<3;j++)
            K2[i][j] = K[i][0]*K[0][j]+K[i][1]*K[1][j]+K[i][2]*K[2][j];
    float T[4][4];
    float Vm[3][3];
    for (int i=0;i<3;i++)
        for (int j=0;j<3;j++){
            float I = (i==j)?1.0f:0.0f;
            T[i][j]  = I + A*K[i][j] + Bc*K2[i][j];
            Vm[i][j] = I + Bc*K[i][j] + Cc*K2[i][j];
        }
    T[0][3] = Vm[0][0]*v0+Vm[0][1]*v1+Vm[0][2]*v2;
    T[1][3] = Vm[1][0]*v0+Vm[1][1]*v1+Vm[1][2]*v2;
    T[2][3] = Vm[2][0]*v0+Vm[2][1]*v1+Vm[2][2]*v2;
    T[3][0]=0.0f; T[3][1]=0.0f; T[3][2]=0.0f; T[3][3]=1.0f;

    float* Pg = g_pose + b*16;
    float Pold[4][4];
    for (int i=0;i<4;i++)
        for (int j=0;j<4;j++) Pold[i][j] = Pg[i*4+j];
    float Pn[4][4];
    for (int i=0;i<4;i++)
        for (int j=0;j<4;j++){
            float s=0.0f;
            for (int k=0;k<4;k++) s += T[i][k]*Pold[k][j];
            Pn[i][j]=s;
        }
    for (int i=0;i<4;i++)
        for (int j=0;j<4;j++) Pg[i*4+j] = Pn[i][j];

    for (int k=0;k<27;k++) a[k]=0.0;

    if (write_out){
        for (int i=0;i<4;i++)
            for (int j=0;j<4;j++)
                out[b*16 + i*4 + j] = Pn[i][j];
    }
}

// extract {I0,gx,gy} for channel c (0..3) from the two packed uint4s
__device__ __forceinline__ void get3(const uint4& qa, const uint4& qb, int c,
                                     float& I, float& gx, float& gy) {
    const __half2* h = (c < 2) ? (const __half2*)&qa : (const __half2*)&qb;
    int s = (c & 1) * 2;
    float2 p = __half22float2(h[s]);
    float2 q = __half22float2(h[s+1]);
    I = p.x; gx = p.y; gy = q.x;
}

__global__ void __launch_bounds__(256,4) accumsolve_kernel(
    const float* __restrict__ I1, const float* __restrict__ depth1,
    const float* __restrict__ intr, float* __restrict__ out, int write_out)
{
    int tid  = threadIdx.x;
    int lpix = tid & (PIXPB-1);
    int cg   = tid >> 7;                 // channel group: 0 -> ch 0..3 + ICP, 1 -> ch 4..7
    int b    = blockIdx.y;

    const float* P = g_pose + b*16;
    float R00=P[0],  R01=P[1],  R02=P[2],  t0=P[3];
    float R10=P[4],  R11=P[5],  R12=P[6],  t1=P[7];
    float R20=P[8],  R21=P[9],  R22=P[10], t2=P[11];

    float fx = intr[b*4+0], fy = intr[b*4+1], cx = intr[b*4+2], cy = intr[b*4+3];

    float acc[27];
    #pragma unroll
    for (int k=0;k<27;k++) acc[k]=0.0f;

    #pragma unroll 1
    for (int p=0;p<PPT;p++){
        int pix = blockIdx.x*(PIXPB*PPT) + p*PIXPB + lpix;
        int x = pix & (WW-1), y = pix / WW;

        float d1 = depth1[b*HWSZ+pix];
        float d0c = g_icp[b*HWSZ+pix].w;

        float Vx = ((float)x-cx)/fx*d1;
        float Vy = ((float)y-cy)/fy*d1;
        float Vz = d1;

        float Xx = R00*Vx+R01*Vy+R02*Vz+t0;
        float Xy = R10*Vx+R11*Vy+R12*Vz+t1;
        float Xz = R20*Vx+R21*Vy+R22*Vz+t2;

        bool  valid0 = Xz > 1e-8f;
        float zs = (fabsf(Xz) > 1e-8f) ? Xz : 1e-8f;
        float iz = __fdividef(1.0f, zs);
        float u = fx*Xx*iz + cx;
        float v = fy*Xy*iz + cy;

        bool valid = (u>0.0f) && (u<(float)(WW-1)) && (v>0.0f) && (v<(float)(HH-1))
                   && valid0 && (d0c>0.0f) && (d1>0.0f);
        float vmask = valid ? 1.0f : 0.0f;

        // branchless clamped bilinear setup
        int iu = min(max((int)floorf(u), 0), WW-2);
        int iv = min(max((int)floorf(v), 0), HH-2);
        float du = fminf(fmaxf(u - (float)iu, 0.0f), 1.0f);
        float dv = fminf(fmaxf(v - (float)iv, 0.0f), 1.0f);
        float w00=(1.0f-du)*(1.0f-dv)*vmask, w10=du*(1.0f-dv)*vmask;
        float w01=(1.0f-du)*dv*vmask,        w11=du*dv*vmask;
        int i00 = iv*WW+iu;

        float a  = Xx*iz, bq = Xy*iz;
        float fxz = fx*iz, fyz = fy*iz;
        // A = row0 of Jw (A[4]=0), B = row1 of Jw (B[3]=0)
        float Av[6] = { -fx*a*bq,         fx*(1.0f+a*a), -fx*bq, fxz, 0.0f, -fxz*a };
        float Bv[6] = { -fy*(1.0f+bq*bq), fy*a*bq,        fy*a,  0.0f, fyz, -fyz*bq };

        // front-load the 4 coalesced I1 reads for this channel group
        const float*  i1b = I1 + (size_t)(b*CC + cg*4)*HWSZ;
        float i1v[4];
        #pragma unroll
        for (int c=0;c<4;c++) i1v[c] = i1b[(size_t)c*HWSZ + pix];

        // ---- photometric: 8 x LDG.128 fetch all 4 channels at 4 corners ----
        const uint4* pk = g_packh + (size_t)(b*2+cg)*HWSZ*2;
        uint4 q00a = pk[(size_t)2*i00],        q00b = pk[(size_t)2*i00+1];
        uint4 q10a = pk[(size_t)2*(i00+1)],    q10b = pk[(size_t)2*(i00+1)+1];
        uint4 q01a = pk[(size_t)2*(i00+WW)],   q01b = pk[(size_t)2*(i00+WW)+1];
        uint4 q11a = pk[(size_t)2*(i00+WW+1)], q11b = pk[(size_t)2*(i00+WW+1)+1];

        float Sxx=0.f, Sxy=0.f, Syy=0.f, Srx=0.f, Sry=0.f;
        #pragma unroll
        for (int c=0;c<4;c++){
            float I00,gx00,gy00, I10,gx10,gy10, I01,gx01,gy01, I11,gx11,gy11;
            get3(q00a,q00b,c, I00,gx00,gy00);
            get3(q10a,q10b,c, I10,gx10,gy10);
            get3(q01a,q01b,c, I01,gx01,gy01);
            get3(q11a,q11b,c, I11,gx11,gy11);
            float s  = w00*I00  + w10*I10  + w01*I01  + w11*I11;
            float gx = w00*gx00 + w10*gx10 + w01*gx01 + w11*gx11;
            float gy = w00*gy00 + w10*gy10 + w01*gy01 + w11*gy11;
            float r = i1v[c] - s;
            float ar = fabsf(r);
            float w  = (ar <= 0.5f) ? 1.0f : __fdividef(0.5f, fmaxf(ar, 1e-12f));
            Sxx += w*gx*gx;
            Sxy += w*gx*gy;
            Syy += w*gy*gy;
            Srx += w*r*gx;
            Sry += w*r*gy;
        }

        {
            #pragma unroll
            for (int i=0;i<6;i++) acc[i] += Srx*Av[i] + Sry*Bv[i];
            int k=6;
            #pragma unroll
            for (int i=0;i<6;i++){
                float xA = Sxx*Av[i] + Sxy*Bv[i];
                float xB = Sxy*Av[i] + Syy*Bv[i];
                #pragma unroll
                for (int j=i;j<6;j++){
                    acc[k] += xA*Av[j] + xB*Bv[j];
                    k++;
                }
            }
        }

        // ---- ICP channel (group 0 only; warp-uniform branch) ----
        if (cg == 0) {
            const float4* ip = g_icp + b*HWSZ;
            float4 e00 = ip[i00];
            float4 e10 = ip[i00+1];
            float4 e01 = ip[i00+WW];
            float4 e11 = ip[i00+WW+1];

            float pxl = ((float)iu    -cx)/fx, pxr = ((float)(iu+1)-cx)/fx;
            float pyt = ((float)iv    -cy)/fy, pyb = ((float)(iv+1)-cy)/fy;
            float rVx = w00*pxl*e00.w + w10*pxr*e10.w + w01*pxl*e01.w + w11*pxr*e11.w;
            float rVy = w00*pyt*e00.w + w10*pyt*e10.w + w01*pyb*e01.w + w11*pyb*e11.w;
            float rVz = w00*e00.w + w10*e10.w + w01*e01.w + w11*e11.w;

            float rNx = w00*e00.x + w10*e10.x + w01*e01.x + w11*e11.x;
            float rNy = w00*e00.y + w10*e10.y + w01*e01.y + w11*e11.y;
            float rNz = w00*e00.z + w10*e10.z + w01*e01.z + w11*e11.z;

            float dfx = Xx - rVx, dfy = Xy - rVy, dfz = Xz - rVz;
            float dn2 = dfx*dfx+dfy*dfy+dfz*dfz + 1e-12f;
            bool occ = dn2 > 0.01f;    // dn>0.1  (inviews == inb for contributing pixels)

            float nR0 = rNx*R00 + rNy*R10 + rNz*R20;
            float nR1 = rNx*R01 + rNy*R11 + rNz*R21;
            float nR2 = rNx*R02 + rNy*R12 + rNz*R22;

            float res = rNx*dfx + rNy*dfy + rNz*dfz;

            float sd0 = d1 * (5.5f/525.0f);
            float sd2 = d1*d1 * (0.4f/(525.0f*1.2f));
            float cov = (nR0*nR0 + nR1*nR1)*sd0*sd0 + nR2*nR2*sd2*sd2;
            float sigma = sqrtf(cov + 1e-8f);
            float isig = __fdividef(1.0f, sigma + 1e-8f);

            res *= isig;
            if (occ) res = 1e-6f;

            float Jr0 = nR1*Vz - nR2*Vy;
            float Jr1 = nR2*Vx - nR0*Vz;
            float Jr2 = nR0*Vy - nR1*Vx;
            float gis = GEOMW*isig;
            float J[6] = { -Jr0*gis, -Jr1*gis, -Jr2*gis, nR0*gis, nR1*gis, nR2*gis };
            float r = -GEOMW * res;
            float ar = fabsf(r);
            float w  = (ar <= 0.5f) ? 1.0f : __fdividef(0.5f, fmaxf(ar, 1e-12f));
            float wr = w*r;
            #pragma unroll
            for (int i=0;i<6;i++) acc[i] += J[i]*wr;
            int k=6;
            #pragma unroll
            for (int i=0;i<6;i++){
                float wJi = w*J[i];
                #pragma unroll
                for (int j=i;j<6;j++){
                    acc[k] += wJi*J[j];
                    k++;
                }
            }
        }
    }

    // ---- reduction: 4-level shuffles (16-lane halves) -> shared float atomics
    //      -> one double atomic per value per block ----
    __shared__ float  sredf[27];
    __shared__ bool amLast;
    if (tid < 27) sredf[tid] = 0.0f;
    __syncthreads();
    #pragma unroll
    for (int k=0;k<27;k++){
        float val = acc[k];
        val += __shfl_down_sync(0xffffffffu, val, 8);
        val += __shfl_down_sync(0xffffffffu, val, 4);
        val += __shfl_down_sync(0xffffffffu, val, 2);
        val += __shfl_down_sync(0xffffffffu, val, 1);
        if ((tid & 15) == 0) atomicAdd(&sredf[k], val);  // lanes 0 and 16
    }
    __syncthreads();
    if (tid < 27) atomicAdd(&g_acc[b*27+tid], (double)sredf[tid]);

    // ---- last block for this batch performs the solve ----
    __threadfence();
    __syncthreads();
    if (tid == 0){
        int prev = atomicAdd(&g_cnt[b], 1);
        amLast = (prev == NBLKX-1);
    }
    __syncthreads();
    if (amLast && tid == 0){
        __threadfence();
        solve_batch(b, out, write_out);
        g_cnt[b] = 0;
    }
}

extern "C" void kernel_launch(void* const* d_in, const int* in_sizes, int n_in,
                              void* d_out, int out_size) {
    const float* pose   = (const float*)d_in[0];
    const float* I0     = (const float*)d_in[1];
    const float* I1     = (const float*)d_in[2];
    const float* intr   = (const float*)d_in[5];
    const float* depth0 = (const float*)d_in[6];
    const float* depth1 = (const float*)d_in[7];
    (void)in_sizes; (void)n_in; (void)out_size;

    dim3 pgrid(HWSZ/256, BB);
    precompute_kernel<<<pgrid,256>>>(I0, depth0, intr, pose);
    dim3 agrid(NBLKX, BB);
    for (int it=0; it<3; it++){
        accumsolve_kernel<<<agrid,256>>>(I1, depth1, intr, (float*)d_out, (it==2) ? 1 : 0);
    }
}